// round 5
// baseline (speedup 1.0000x reference)
#include <cuda_runtime.h>
#include <cuda_fp16.h>
#include <cstdint>
#include <math.h>

// Problem constants
#define B_ 8
#define N_ 2048
#define D_ 512
#define E_ 512

static constexpr long QKV_ELEMS  = (long)B_ * N_ * D_;   // 8,388,608
static constexpr long W_ELEMS    = (long)E_ * D_;        // 262,144
static constexpr long ATTN_ELEMS = (long)B_ * N_ * N_;   // 33,554,432

#define SQUANT 5120.0f        // int16 quantization scale (range ~ +-6.4 sigma)

// ---------------- scratch (static device arrays; allocation-guard safe) ----
// int8 limb arrays for q/k path
__device__ int8_t g_q8h[QKV_ELEMS],  g_q8l[QKV_ELEMS];
__device__ int8_t g_k8h[QKV_ELEMS],  g_k8l[QKV_ELEMS];
__device__ int8_t g_Wq8h[W_ELEMS],   g_Wq8l[W_ELEMS];
__device__ int8_t g_Wk8h[W_ELEMS],   g_Wk8l[W_ELEMS];
__device__ int8_t g_qp8h[QKV_ELEMS], g_qp8l[QKV_ELEMS];
__device__ int8_t g_kp8h[QKV_ELEMS], g_kp8l[QKV_ELEMS];
// fp16 path (v projection + attention@v)
__device__ __half g_vh[QKV_ELEMS],  g_vl[QKV_ELEMS];
__device__ __half g_Wvh[W_ELEMS],   g_Wvl[W_ELEMS];
__device__ __half g_vpth[QKV_ELEMS], g_vptl[QKV_ELEMS];   // transposed [b][e][n]
__device__ __half g_ah[ATTN_ELEMS], g_al[ATTN_ELEMS];

// ---------------- PTX helpers ----------------------------------------------
__device__ __forceinline__ uint32_t smem_to_u32(const void* p) {
    uint32_t a;
    asm("{ .reg .u64 t; cvta.to.shared.u64 t, %1; cvt.u32.u64 %0, t; }" : "=r"(a) : "l"(p));
    return a;
}

#define CP_ASYNC16(smem_u32, gptr) \
    asm volatile("cp.async.cg.shared.global [%0], [%1], 16;" :: "r"(smem_u32), "l"(gptr) : "memory")
#define CP_ASYNC_COMMIT() asm volatile("cp.async.commit_group;" ::: "memory")
#define CP_ASYNC_WAIT1()  asm volatile("cp.async.wait_group 1;" ::: "memory")

__device__ __forceinline__ void ldsm_x4(uint32_t* r, uint32_t addr) {
    asm volatile("ldmatrix.sync.aligned.m8n8.x4.shared.b16 {%0,%1,%2,%3}, [%4];"
        : "=r"(r[0]), "=r"(r[1]), "=r"(r[2]), "=r"(r[3]) : "r"(addr));
}

__device__ __forceinline__ void mma16816(float* c, const uint32_t* a, const uint32_t* b) {
    asm volatile(
        "mma.sync.aligned.m16n8k16.row.col.f32.f16.f16.f32 "
        "{%0,%1,%2,%3}, {%4,%5,%6,%7}, {%8,%9}, {%0,%1,%2,%3};"
        : "+f"(c[0]), "+f"(c[1]), "+f"(c[2]), "+f"(c[3])
        : "r"(a[0]), "r"(a[1]), "r"(a[2]), "r"(a[3]), "r"(b[0]), "r"(b[1]));
}

__device__ __forceinline__ void imma16832(int* c, const uint32_t* a, const uint32_t* b) {
    asm volatile(
        "mma.sync.aligned.m16n8k32.row.col.s32.s8.s8.s32 "
        "{%0,%1,%2,%3}, {%4,%5,%6,%7}, {%8,%9}, {%0,%1,%2,%3};"
        : "+r"(c[0]), "+r"(c[1]), "+r"(c[2]), "+r"(c[3])
        : "r"(a[0]), "r"(a[1]), "r"(a[2]), "r"(a[3]), "r"(b[0]), "r"(b[1]));
}

// ===========================================================================
// INT16 (2 x s8 limb) GEMM:  C = alpha * A @ B^T  where A,B are int16 values
// stored as s8 limb pairs (X = 256*h + l). Computes h*h (weight 65536) and
// (h*l + l*h) (weight 256); drops l*l.
// A: [M,K] row-major K-contig, B: [N,K] row-major K-contig (s8 limbs).
// mode 0: C0 fp32 [M,N] (+ z*sC); mode 3: C0/C1 s8 limb pair [M,N] requantized
// with scale sq.
// Tile 128x128, BK=64 (s8), 8 warps (warp tile 32x64: 4M x 2N), 3-stage ring.
// ===========================================================================
#define I_ROWB 80                          // 64 s8 + 16B pad
#define I_TILE_B (128 * I_ROWB)            // 10240
#define I_STAGE_B (4 * I_TILE_B)           // 40960: Ah, Al, Bh, Bl
#define I_OFF_AL (I_TILE_B)
#define I_OFF_BH (2 * I_TILE_B)
#define I_OFF_BL (3 * I_TILE_B)
#define I_NSTAGE 3
#define I_SMEM_TOTAL (I_NSTAGE * I_STAGE_B)   // 122880

__global__ __launch_bounds__(256, 1) void gemm_i8(
    const int8_t* __restrict__ Ah, const int8_t* __restrict__ Al,
    const int8_t* __restrict__ Bh, const int8_t* __restrict__ Bl,
    int M, int N, int K,
    long sA, long sB, long sC,
    float alpha, float sq, int mode,
    void* __restrict__ C0, void* __restrict__ C1)
{
    extern __shared__ char smem[];
    const uint32_t smem_base = smem_to_u32(smem);
    const int tid  = threadIdx.x;
    const int wid  = tid >> 5;
    const int lane = tid & 31;
    const int wm = wid & 3;        // 4 warps along M (32 rows each)
    const int wn = wid >> 2;       // 2 warps along N (64 cols each)
    const int z = blockIdx.z;

    Ah += (long)z * sA;  Al += (long)z * sA;
    Bh += (long)z * sB;  Bl += (long)z * sB;

    const int m0 = blockIdx.y * 128;
    const int n0 = blockIdx.x * 128;

    int acc_hh[2][8][4], acc_cr[2][8][4];
    #pragma unroll
    for (int i = 0; i < 2; i++)
        #pragma unroll
        for (int j = 0; j < 8; j++)
            #pragma unroll
            for (int c = 0; c < 4; c++) { acc_hh[i][j][c] = 0; acc_cr[i][j][c] = 0; }

    const int nslab = K / 64;
    const int lrow = tid >> 2;        // 0..63
    const int lch  = tid & 3;         // 16B chunk within 64B row

    auto load_slab = [&](int s) {
        const long koff = (long)s * 64 + lch * 16;
        const uint32_t st = smem_base + (uint32_t)(s % I_NSTAGE) * I_STAGE_B;
        const uint32_t so = (uint32_t)(lrow * I_ROWB + lch * 16);
        #pragma unroll
        for (int i = 0; i < 2; i++) {
            const int r = lrow + 64 * i;
            const long ga = (long)(m0 + r) * K + koff;
            const long gb = (long)(n0 + r) * K + koff;
            const uint32_t ro = so + (uint32_t)i * (64 * I_ROWB);
            CP_ASYNC16(st +            ro, Ah + ga);
            CP_ASYNC16(st + I_OFF_AL + ro, Al + ga);
            CP_ASYNC16(st + I_OFF_BH + ro, Bh + gb);
            CP_ASYNC16(st + I_OFF_BL + ro, Bl + gb);
        }
    };

    load_slab(0); CP_ASYNC_COMMIT();
    if (nslab > 1) load_slab(1);
    CP_ASYNC_COMMIT();

    const int am = lane & 15;
    const int asel = (lane >> 4) * 16;            // byte offset within k32
    const int bn = ((lane >> 4) << 3) + (lane & 7);
    const int bsel = ((lane >> 3) & 1) * 16;

    for (int s = 0; s < nslab; s++) {
        CP_ASYNC_WAIT1();
        __syncthreads();

        if (s + 2 < nslab) load_slab(s + 2);
        CP_ASYNC_COMMIT();

        const uint32_t st = smem_base + (uint32_t)(s % I_NSTAGE) * I_STAGE_B;
        #pragma unroll
        for (int k32 = 0; k32 < 2; k32++) {
            uint32_t rah[2][4], ral[2][4];
            #pragma unroll
            for (int mi = 0; mi < 2; mi++) {
                const uint32_t ao =
                    (uint32_t)((wm * 32 + mi * 16 + am) * I_ROWB + k32 * 32 + asel);
                ldsm_x4(rah[mi], st + ao);
                ldsm_x4(ral[mi], st + I_OFF_AL + ao);
            }
            #pragma unroll
            for (int pair = 0; pair < 4; pair++) {
                const uint32_t bo =
                    (uint32_t)((wn * 64 + pair * 16 + bn) * I_ROWB + k32 * 32 + bsel);
                uint32_t th[4], tl[4];
                ldsm_x4(th, st + I_OFF_BH + bo);
                ldsm_x4(tl, st + I_OFF_BL + bo);
                #pragma unroll
                for (int nj = 0; nj < 2; nj++) {
                    const uint32_t bh2[2] = { th[nj * 2], th[nj * 2 + 1] };
                    const uint32_t bl2[2] = { tl[nj * 2], tl[nj * 2 + 1] };
                    #pragma unroll
                    for (int mi = 0; mi < 2; mi++) {
                        imma16832(acc_hh[mi][pair * 2 + nj], rah[mi], bh2);
                        imma16832(acc_cr[mi][pair * 2 + nj], rah[mi], bl2);
                        imma16832(acc_cr[mi][pair * 2 + nj], ral[mi], bh2);
                    }
                }
            }
        }
    }

    // -------- epilogue --------
    const int rq = lane >> 2;
    const int cq = (lane & 3) * 2;
    #pragma unroll
    for (int mi = 0; mi < 2; mi++) {
        #pragma unroll
        for (int ni = 0; ni < 8; ni++) {
            const int mA = m0 + wm * 32 + mi * 16 + rq;
            const int mB = mA + 8;
            const int n  = n0 + wn * 64 + ni * 8 + cq;
            float vv[4];
            #pragma unroll
            for (int c = 0; c < 4; c++)
                vv[c] = (65536.0f * (float)acc_hh[mi][ni][c]
                         + 256.0f * (float)acc_cr[mi][ni][c]) * alpha;
            if (mode == 0) {
                float* Cf = (float*)C0 + (size_t)z * sC;
                *(float2*)(Cf + (size_t)mA * N + n) = make_float2(vv[0], vv[1]);
                *(float2*)(Cf + (size_t)mB * N + n) = make_float2(vv[2], vv[3]);
            } else {
                char2 hc[2], lc[2];
                #pragma unroll
                for (int c = 0; c < 4; c++) {
                    int X = __float2int_rn(vv[c] * sq);
                    X = max(-32640, min(32639, X));
                    const int h = (X + 128) >> 8;
                    const int l = X - (h << 8);
                    ((char*)&hc[0])[c] = (char)h;
                    ((char*)&lc[0])[c] = (char)l;
                }
                *(char2*)((int8_t*)C0 + (size_t)mA * N + n) = hc[0];
                *(char2*)((int8_t*)C0 + (size_t)mB * N + n) = hc[1];
                *(char2*)((int8_t*)C1 + (size_t)mA * N + n) = lc[0];
                *(char2*)((int8_t*)C1 + (size_t)mB * N + n) = lc[1];
            }
        }
    }
}

// ===========================================================================
// 3-term fp16-split GEMM (unchanged from R4): used for v projection + GEMM3
// ===========================================================================
#define BKH 32
#define ROWH 40
#define ROWB 80
#define A_TILE_B (128 * ROWB)
#define B_TILE_B (256 * ROWB)
#define STAGE_B (2 * A_TILE_B + 2 * B_TILE_B)
#define OFF_AL (A_TILE_B)
#define OFF_BH (2 * A_TILE_B)
#define OFF_BL (2 * A_TILE_B + B_TILE_B)
#define NSTAGE 3
#define GEMM_SMEM_TOTAL (NSTAGE * STAGE_B)

__global__ __launch_bounds__(256, 1) void gemm3t(
    const __half* __restrict__ Ah, const __half* __restrict__ Al,
    const __half* __restrict__ Bh, const __half* __restrict__ Bl,
    int M, int N, int K,
    long sA, long sB, long sC,
    float alpha, int mode,
    void* __restrict__ C0, void* __restrict__ C1)
{
    extern __shared__ char smem[];
    const uint32_t smem_base = smem_to_u32(smem);
    const int tid  = threadIdx.x;
    const int wid  = tid >> 5;
    const int lane = tid & 31;
    const int wm = wid & 1;
    const int wn = wid >> 1;
    const int z = blockIdx.z;

    Ah += (long)z * sA;  Al += (long)z * sA;
    Bh += (long)z * sB;  Bl += (long)z * sB;

    const int m0 = blockIdx.y * 128;
    const int n0 = blockIdx.x * 256;

    float acc[4][8][4];
    #pragma unroll
    for (int i = 0; i < 4; i++)
        #pragma unroll
        for (int j = 0; j < 8; j++)
            #pragma unroll
            for (int c = 0; c < 4; c++) acc[i][j][c] = 0.0f;

    const int nslab = K / BKH;
    const int lrow = tid >> 2;
    const int lch  = tid & 3;

    auto load_slab = [&](int s) {
        const long koff = (long)s * BKH + lch * 8;
        const uint32_t st = smem_base + (uint32_t)(s % NSTAGE) * STAGE_B;
        const uint32_t so = (uint32_t)(lrow * ROWB + lch * 16);
        #pragma unroll
        for (int i = 0; i < 2; i++) {
            const int r = lrow + 64 * i;
            const long g = (long)(m0 + r) * K + koff;
            CP_ASYNC16(st +          so + i * (64 * ROWB), Ah + g);
            CP_ASYNC16(st + OFF_AL + so + i * (64 * ROWB), Al + g);
        }
        #pragma unroll
        for (int i = 0; i < 4; i++) {
            const int r = lrow + 64 * i;
            const long g = (long)(n0 + r) * K + koff;
            CP_ASYNC16(st + OFF_BH + so + i * (64 * ROWB), Bh + g);
            CP_ASYNC16(st + OFF_BL + so + i * (64 * ROWB), Bl + g);
        }
    };

    load_slab(0); CP_ASYNC_COMMIT();
    if (nslab > 1) load_slab(1);
    CP_ASYNC_COMMIT();

    const int am = lane & 15;
    const int ac = (lane >> 4) << 3;
    const int bn = ((lane >> 4) << 3) + (lane & 7);
    const int bc = ((lane >> 3) & 1) << 3;

    for (int s = 0; s < nslab; s++) {
        CP_ASYNC_WAIT1();
        __syncthreads();

        if (s + 2 < nslab) load_slab(s + 2);
        CP_ASYNC_COMMIT();

        const uint32_t st = smem_base + (uint32_t)(s % NSTAGE) * STAGE_B;
        #pragma unroll
        for (int k16 = 0; k16 < 2; k16++) {
            uint32_t ra_h[4][4], ra_l[4][4];
            #pragma unroll
            for (int mi = 0; mi < 4; mi++) {
                const uint32_t ao =
                    (uint32_t)((wm * 64 + mi * 16 + am) * ROWH + k16 * 16 + ac) * 2;
                ldsm_x4(ra_h[mi], st + ao);
                ldsm_x4(ra_l[mi], st + OFF_AL + ao);
            }
            #pragma unroll
            for (int pair = 0; pair < 4; pair++) {
                const uint32_t bo =
                    (uint32_t)((wn * 64 + pair * 16 + bn) * ROWH + k16 * 16 + bc) * 2;
                uint32_t th[4], tl[4];
                ldsm_x4(th, st + OFF_BH + bo);
                ldsm_x4(tl, st + OFF_BL + bo);
                #pragma unroll
                for (int nj = 0; nj < 2; nj++) {
                    const uint32_t bh2[2] = { th[nj * 2], th[nj * 2 + 1] };
                    const uint32_t bl2[2] = { tl[nj * 2], tl[nj * 2 + 1] };
                    #pragma unroll
                    for (int mi = 0; mi < 4; mi++) {
                        float* a = acc[mi][pair * 2 + nj];
                        mma16816(a, ra_h[mi], bh2);
                        mma16816(a, ra_h[mi], bl2);
                        mma16816(a, ra_l[mi], bh2);
                    }
                }
            }
        }
    }

    const int rq = lane >> 2;
    const int cq = (lane & 3) * 2;
    #pragma unroll
    for (int mi = 0; mi < 4; mi++) {
        #pragma unroll
        for (int ni = 0; ni < 8; ni++) {
            const int mA = m0 + wm * 64 + mi * 16 + rq;
            const int mB = mA + 8;
            const int n  = n0 + wn * 64 + ni * 8 + cq;
            const float v0 = acc[mi][ni][0] * alpha;
            const float v1 = acc[mi][ni][1] * alpha;
            const float v2 = acc[mi][ni][2] * alpha;
            const float v3 = acc[mi][ni][3] * alpha;
            if (mode == 0) {
                float* Cf = (float*)C0 + (size_t)z * sC;
                *(float2*)(Cf + (size_t)mA * N + n) = make_float2(v0, v1);
                *(float2*)(Cf + (size_t)mB * N + n) = make_float2(v2, v3);
            } else {
                // transposed fp16 hi/lo store: C[b][e][n]
                #pragma unroll
                for (int e = 0; e < 4; e++) {
                    const int m = (e < 2) ? mA : mB;
                    const int nn2 = n + (e & 1);
                    const float val = (e == 0) ? v0 : (e == 1) ? v1 : (e == 2) ? v2 : v3;
                    const int bi = m >> 11;
                    const int mm = m & (N_ - 1);
                    const __half h = __float2half_rn(val);
                    const __half l = __float2half_rn(val - __half2float(h));
                    const size_t idx = ((size_t)bi * E_ + nn2) * N_ + mm;
                    ((__half*)C0)[idx] = h;
                    ((__half*)C1)[idx] = l;
                }
            }
        }
    }
}

// ---------------------------------------------------------------------------
// elementwise splits
// ---------------------------------------------------------------------------
__device__ __forceinline__ void split_store4(__half* h, __half* l, size_t idx, float4 v) {
    const __half h0 = __float2half_rn(v.x);
    const __half h1 = __float2half_rn(v.y);
    const __half h2 = __float2half_rn(v.z);
    const __half h3 = __float2half_rn(v.w);
    const __half l0 = __float2half_rn(v.x - __half2float(h0));
    const __half l1 = __float2half_rn(v.y - __half2float(h1));
    const __half l2 = __float2half_rn(v.z - __half2float(h2));
    const __half l3 = __float2half_rn(v.w - __half2float(h3));
    __half2* hp = (__half2*)(h + idx);
    __half2* lp = (__half2*)(l + idx);
    hp[0] = __halves2half2(h0, h1);  hp[1] = __halves2half2(h2, h3);
    lp[0] = __halves2half2(l0, l1);  lp[1] = __halves2half2(l2, l3);
}

__global__ __launch_bounds__(256) void split_fp32(
    const float* __restrict__ x, __half* __restrict__ h,
    __half* __restrict__ l, long n4)
{
    for (long i = blockIdx.x * 256 + threadIdx.x; i < n4; i += (long)gridDim.x * 256) {
        float4 v = ((const float4*)x)[i];
        split_store4(h, l, (size_t)i * 4, v);
    }
}

__global__ __launch_bounds__(256) void split_i8(
    const float* __restrict__ x, int8_t* __restrict__ h,
    int8_t* __restrict__ l, long n4)
{
    for (long i = blockIdx.x * 256 + threadIdx.x; i < n4; i += (long)gridDim.x * 256) {
        float4 v = ((const float4*)x)[i];
        const float vv[4] = { v.x, v.y, v.z, v.w };
        char hc[4], lc[4];
        #pragma unroll
        for (int c = 0; c < 4; c++) {
            int X = __float2int_rn(vv[c] * SQUANT);
            X = max(-32640, min(32639, X));
            const int hh = (X + 128) >> 8;
            hc[c] = (char)hh;
            lc[c] = (char)(X - (hh << 8));
        }
        *(char4*)(h + i * 4) = *(char4*)hc;
        *(char4*)(l + i * 4) = *(char4*)lc;
    }
}

// ---------------------------------------------------------------------------
// fused softmax (in place, fp32) + fp16 hi/lo emission. One block per row.
// ---------------------------------------------------------------------------
__global__ __launch_bounds__(256) void softmax_fused(
    float* __restrict__ attn, __half* __restrict__ ah, __half* __restrict__ al)
{
    const size_t row = blockIdx.x;
    float* p = attn + row * N_;
    const int t = threadIdx.x;
    __shared__ float red[8];

    float4 va = ((const float4*)p)[t];
    float4 vb = ((const float4*)p)[t + 256];

    float vmax = fmaxf(fmaxf(fmaxf(va.x, va.y), fmaxf(va.z, va.w)),
                       fmaxf(fmaxf(vb.x, vb.y), fmaxf(vb.z, vb.w)));
    #pragma unroll
    for (int o = 16; o > 0; o >>= 1) vmax = fmaxf(vmax, __shfl_xor_sync(0xFFFFFFFF, vmax, o));
    if ((t & 31) == 0) red[t >> 5] = vmax;
    __syncthreads();
    float m = fmaxf(fmaxf(fmaxf(red[0], red[1]), fmaxf(red[2], red[3])),
                    fmaxf(fmaxf(red[4], red[5]), fmaxf(red[6], red[7])));
    __syncthreads();

    va.x = __expf(va.x - m); va.y = __expf(va.y - m); va.z = __expf(va.z - m); va.w = __expf(va.w - m);
    vb.x = __expf(vb.x - m); vb.y = __expf(vb.y - m); vb.z = __expf(vb.z - m); vb.w = __expf(vb.w - m);

    float sum = va.x + va.y + va.z + va.w + vb.x + vb.y + vb.z + vb.w;
    #pragma unroll
    for (int o = 16; o > 0; o >>= 1) sum += __shfl_xor_sync(0xFFFFFFFF, sum, o);
    if ((t & 31) == 0) red[t >> 5] = sum;
    __syncthreads();
    const float inv = 1.0f / (red[0] + red[1] + red[2] + red[3] + red[4] + red[5] + red[6] + red[7]);

    va.x *= inv; va.y *= inv; va.z *= inv; va.w *= inv;
    vb.x *= inv; vb.y *= inv; vb.z *= inv; vb.w *= inv;

    ((float4*)p)[t]       = va;
    ((float4*)p)[t + 256] = vb;
    split_store4(ah, al, row * N_ + (size_t)t * 4,        va);
    split_store4(ah, al, row * N_ + 1024 + (size_t)t * 4, vb);
}

// ---------------------------------------------------------------------------
extern "C" void kernel_launch(void* const* d_in, const int* in_sizes, int n_in,
                              void* d_out, int out_size)
{
    const float* q  = (const float*)d_in[0];
    const float* k  = (const float*)d_in[1];
    const float* v  = (const float*)d_in[2];
    const float* Wq = (const float*)d_in[3];
    const float* Wk = (const float*)d_in[4];
    const float* Wv = (const float*)d_in[5];

    float* out  = (float*)d_out;                 // [B, N, E]
    float* attn = out + (long)B_ * N_ * E_;      // [B, N, N]

    cudaFuncSetAttribute(gemm3t, cudaFuncAttributeMaxDynamicSharedMemorySize, GEMM_SMEM_TOTAL);
    cudaFuncSetAttribute(gemm_i8, cudaFuncAttributeMaxDynamicSharedMemorySize, I_SMEM_TOTAL);

    int8_t *q8h, *q8l, *k8h, *k8l, *Wq8h, *Wq8l, *Wk8h, *Wk8l;
    int8_t *qp8h, *qp8l, *kp8h, *kp8l;
    __half *vh, *vl, *Wvh, *Wvl, *vpth, *vptl, *ah, *al;
    cudaGetSymbolAddress((void**)&q8h, g_q8h);   cudaGetSymbolAddress((void**)&q8l, g_q8l);
    cudaGetSymbolAddress((void**)&k8h, g_k8h);   cudaGetSymbolAddress((void**)&k8l, g_k8l);
    cudaGetSymbolAddress((void**)&Wq8h, g_Wq8h); cudaGetSymbolAddress((void**)&Wq8l, g_Wq8l);
    cudaGetSymbolAddress((void**)&Wk8h, g_Wk8h); cudaGetSymbolAddress((void**)&Wk8l, g_Wk8l);
    cudaGetSymbolAddress((void**)&qp8h, g_qp8h); cudaGetSymbolAddress((void**)&qp8l, g_qp8l);
    cudaGetSymbolAddress((void**)&kp8h, g_kp8h); cudaGetSymbolAddress((void**)&kp8l, g_kp8l);
    cudaGetSymbolAddress((void**)&vh, g_vh);     cudaGetSymbolAddress((void**)&vl, g_vl);
    cudaGetSymbolAddress((void**)&Wvh, g_Wvh);   cudaGetSymbolAddress((void**)&Wvl, g_Wvl);
    cudaGetSymbolAddress((void**)&vpth, g_vpth); cudaGetSymbolAddress((void**)&vptl, g_vptl);
    cudaGetSymbolAddress((void**)&ah, g_ah);     cudaGetSymbolAddress((void**)&al, g_al);

    const float c_eq  = rsqrtf((float)D_);
    const float scale = rsqrtf((float)E_);
    const float invS2 = 1.0f / (SQUANT * SQUANT);

    // 1) elementwise splits
    split_i8<<<2048, 256>>>(q, q8h, q8l, QKV_ELEMS / 4);
    split_i8<<<2048, 256>>>(k, k8h, k8l, QKV_ELEMS / 4);
    split_i8<<<256, 256>>>(Wq, Wq8h, Wq8l, W_ELEMS / 4);
    split_i8<<<256, 256>>>(Wk, Wk8h, Wk8l, W_ELEMS / 4);
    split_fp32<<<2048, 256>>>(v, vh, vl, QKV_ELEMS / 4);
    split_fp32<<<256, 256>>>(Wv, Wvh, Wvl, W_ELEMS / 4);

    // 2) q/k projections (int16 path): [16384,512] @ W^T, requantized output
    {
        dim3 grid(E_ / 128, (B_ * N_) / 128, 1);
        gemm_i8<<<grid, 256, I_SMEM_TOTAL>>>(q8h, q8l, Wq8h, Wq8l, B_ * N_, E_, D_,
                                             0, 0, 0, c_eq * invS2, SQUANT, 3, qp8h, qp8l);
        gemm_i8<<<grid, 256, I_SMEM_TOTAL>>>(k8h, k8l, Wk8h, Wk8l, B_ * N_, E_, D_,
                                             0, 0, 0, c_eq * invS2, SQUANT, 3, kp8h, kp8l);
    }
    // 2b) v projection (fp16 path), transposed output
    {
        dim3 grid(E_ / 256, (B_ * N_) / 128, 1);
        gemm3t<<<grid, 256, GEMM_SMEM_TOTAL>>>(vh, vl, Wvh, Wvl, B_ * N_, E_, D_,
                                               0, 0, 0, c_eq, 2, vpth, vptl);
    }

    // 3) dots = qp @ kp^T * scale -> attn region (fp32), batched (int16 path)
    {
        dim3 grid(N_ / 128, N_ / 128, B_);
        gemm_i8<<<grid, 256, I_SMEM_TOTAL>>>(qp8h, qp8l, kp8h, kp8l, N_, N_, E_,
                                             (long)N_ * E_, (long)N_ * E_, (long)N_ * N_,
                                             scale * invS2, 0.0f, 0, attn, nullptr);
    }

    // 4) softmax (in place) + fp16 hi/lo split of attn
    softmax_fused<<<B_ * N_, 256>>>(attn, ah, al);

    // 5) out = attn @ vp (fp16 path; vp^T stored [b][e][n], K=N_=2048 contig)
    {
        dim3 grid(E_ / 256, N_ / 128, B_);
        gemm3t<<<grid, 256, GEMM_SMEM_TOTAL>>>(ah, al, vpth, vptl, N_, E_, N_,
                                               (long)N_ * N_, (long)E_ * N_, (long)N_ * E_,
                                               1.0f, 0, out, nullptr);
    }
}

// round 6
// speedup vs baseline: 1.5885x; 1.5885x over previous
#include <cuda_runtime.h>
#include <cuda_fp16.h>
#include <cstdint>
#include <math.h>

// Problem constants
#define B_ 8
#define N_ 2048
#define D_ 512
#define E_ 512

static constexpr long QKV_ELEMS  = (long)B_ * N_ * D_;   // 8,388,608
static constexpr long W_ELEMS    = (long)E_ * D_;        // 262,144
static constexpr long ATTN_ELEMS = (long)B_ * N_ * N_;   // 33,554,432

#define LO_SCALE 2048.0f
#define INV_LO   4.8828125e-4f    // 1/2048

// ---------------- scratch (static device arrays; allocation-guard safe) ----
__device__ __half g_qh[QKV_ELEMS],  g_ql[QKV_ELEMS];
__device__ __half g_kh[QKV_ELEMS],  g_kl[QKV_ELEMS];
__device__ __half g_vh[QKV_ELEMS],  g_vl[QKV_ELEMS];
__device__ __half g_Wqh[W_ELEMS],   g_Wql[W_ELEMS];
__device__ __half g_Wkh[W_ELEMS],   g_Wkl[W_ELEMS];
__device__ __half g_Wvh[W_ELEMS],   g_Wvl[W_ELEMS];
__device__ __half g_qph[QKV_ELEMS], g_qpl[QKV_ELEMS];
__device__ __half g_kph[QKV_ELEMS], g_kpl[QKV_ELEMS];
__device__ __half g_vpth[QKV_ELEMS], g_vptl[QKV_ELEMS];   // transposed [b][e][n]
__device__ __half g_ah[ATTN_ELEMS], g_al[ATTN_ELEMS];

// ---------------- PTX helpers ----------------------------------------------
__device__ __forceinline__ uint32_t smem_to_u32(const void* p) {
    uint32_t a;
    asm("{ .reg .u64 t; cvta.to.shared.u64 t, %1; cvt.u32.u64 %0, t; }" : "=r"(a) : "l"(p));
    return a;
}

#define CP_ASYNC16(smem_u32, gptr) \
    asm volatile("cp.async.cg.shared.global [%0], [%1], 16;" :: "r"(smem_u32), "l"(gptr) : "memory")
#define CP_ASYNC_COMMIT() asm volatile("cp.async.commit_group;" ::: "memory")
#define CP_ASYNC_WAIT1()  asm volatile("cp.async.wait_group 1;" ::: "memory")

__device__ __forceinline__ void ldsm_x4(uint32_t* r, uint32_t addr) {
    asm volatile("ldmatrix.sync.aligned.m8n8.x4.shared.b16 {%0,%1,%2,%3}, [%4];"
        : "=r"(r[0]), "=r"(r[1]), "=r"(r[2]), "=r"(r[3]) : "r"(addr));
}

// fp32-accumulator HMMA (hi*hi product)
__device__ __forceinline__ void mma16816f(float* c, const uint32_t* a, const uint32_t* b) {
    asm volatile(
        "mma.sync.aligned.m16n8k16.row.col.f32.f16.f16.f32 "
        "{%0,%1,%2,%3}, {%4,%5,%6,%7}, {%8,%9}, {%0,%1,%2,%3};"
        : "+f"(c[0]), "+f"(c[1]), "+f"(c[2]), "+f"(c[3])
        : "r"(a[0]), "r"(a[1]), "r"(a[2]), "r"(a[3]), "r"(b[0]), "r"(b[1]));
}

// fp16-accumulator HMMA (cross products, lo-limbs pre-scaled x2048)
__device__ __forceinline__ void mma16816h(uint32_t* c, const uint32_t* a, const uint32_t* b) {
    asm volatile(
        "mma.sync.aligned.m16n8k16.row.col.f16.f16.f16.f16 "
        "{%0,%1}, {%2,%3,%4,%5}, {%6,%7}, {%0,%1};"
        : "+r"(c[0]), "+r"(c[1])
        : "r"(a[0]), "r"(a[1]), "r"(a[2]), "r"(a[3]), "r"(b[0]), "r"(b[1]));
}

// ---------------------------------------------------------------------------
// 3-term fp16-split GEMM:  C = alpha * (Ah + Al/2048) @ (Bh + Bl/2048)^T
// (lo limbs stored pre-scaled x2048; Al*Bl dropped)
// hi*hi -> fp32 accumulator; cross terms -> shared fp16 accumulator.
// A: [M,K] row-major K-contig, B: [N,K] row-major K-contig.
// mode 0: C0 fp32 [M,N] (+ z*sC); mode 1: C0/C1 fp16 hi/lo' [M,N];
// mode 2: C0/C1 fp16 hi/lo' transposed as [b][E_][N_].
// Tile 128x128, BK=32, 512 threads (warp tile 32x32), 3-stage cp.async ring.
// ---------------------------------------------------------------------------
#define BKH 32
#define ROWH 40
#define ROWB 80
#define T_TILE_B (128 * ROWB)              // 10240
#define STAGE_B (4 * T_TILE_B)             // 40960: Ah, Al, Bh, Bl
#define OFF_AL (T_TILE_B)
#define OFF_BH (2 * T_TILE_B)
#define OFF_BL (3 * T_TILE_B)
#define NSTAGE 3
#define GEMM_SMEM_TOTAL (NSTAGE * STAGE_B) // 122880

__global__ __launch_bounds__(512, 1) void gemm3t(
    const __half* __restrict__ Ah, const __half* __restrict__ Al,
    const __half* __restrict__ Bh, const __half* __restrict__ Bl,
    int M, int N, int K,
    long sA, long sB, long sC,
    float alpha, int mode,
    void* __restrict__ C0, void* __restrict__ C1)
{
    extern __shared__ char smem[];
    const uint32_t smem_base = smem_to_u32(smem);
    const int tid  = threadIdx.x;
    const int wid  = tid >> 5;
    const int lane = tid & 31;
    const int wm = wid & 3;        // 4 warps along M (32 rows each)
    const int wn = wid >> 2;       // 4 warps along N (32 cols each)
    const int z = blockIdx.z;

    Ah += (long)z * sA;  Al += (long)z * sA;
    Bh += (long)z * sB;  Bl += (long)z * sB;

    const int m0 = blockIdx.y * 128;
    const int n0 = blockIdx.x * 128;

    float    acc_hh[2][4][4];
    uint32_t acc_cr[2][4][2];
    #pragma unroll
    for (int i = 0; i < 2; i++)
        #pragma unroll
        for (int j = 0; j < 4; j++) {
            #pragma unroll
            for (int c = 0; c < 4; c++) acc_hh[i][j][c] = 0.0f;
            acc_cr[i][j][0] = 0u; acc_cr[i][j][1] = 0u;
        }

    const int nslab = K / BKH;
    const int lrow = tid >> 2;        // 0..127
    const int lch  = tid & 3;         // 16B chunk within 64B row

    // -------- async slab loader: 4 cp.async per thread --------
    auto load_slab = [&](int s) {
        const long koff = (long)s * BKH + lch * 8;
        const uint32_t st = smem_base + (uint32_t)(s % NSTAGE) * STAGE_B;
        const uint32_t so = (uint32_t)(lrow * ROWB + lch * 16);
        const long ga = (long)(m0 + lrow) * K + koff;
        const long gb = (long)(n0 + lrow) * K + koff;
        CP_ASYNC16(st +          so, Ah + ga);
        CP_ASYNC16(st + OFF_AL + so, Al + ga);
        CP_ASYNC16(st + OFF_BH + so, Bh + gb);
        CP_ASYNC16(st + OFF_BL + so, Bl + gb);
    };

    load_slab(0); CP_ASYNC_COMMIT();
    if (nslab > 1) load_slab(1);
    CP_ASYNC_COMMIT();

    const int am = lane & 15;
    const int ac = (lane >> 4) << 3;
    const int bn = ((lane >> 4) << 3) + (lane & 7);
    const int bc = ((lane >> 3) & 1) << 3;

    for (int s = 0; s < nslab; s++) {
        CP_ASYNC_WAIT1();
        __syncthreads();

        if (s + 2 < nslab) load_slab(s + 2);
        CP_ASYNC_COMMIT();

        const uint32_t st = smem_base + (uint32_t)(s % NSTAGE) * STAGE_B;
        #pragma unroll
        for (int k16 = 0; k16 < 2; k16++) {
            // ---- A fragments (hi/lo): 4 ldsm.x4 ----
            uint32_t ra_h[2][4], ra_l[2][4];
            #pragma unroll
            for (int mi = 0; mi < 2; mi++) {
                const uint32_t ao =
                    (uint32_t)((wm * 32 + mi * 16 + am) * ROWH + k16 * 16 + ac) * 2;
                ldsm_x4(ra_h[mi], st + ao);
                ldsm_x4(ra_l[mi], st + OFF_AL + ao);
            }
            // ---- B pairs (16 cols each): 2x2 ldsm.x4 ----
            #pragma unroll
            for (int pair = 0; pair < 2; pair++) {
                const uint32_t bo =
                    (uint32_t)((wn * 32 + pair * 16 + bn) * ROWH + k16 * 16 + bc) * 2;
                uint32_t th[4], tl[4];
                ldsm_x4(th, st + OFF_BH + bo);
                ldsm_x4(tl, st + OFF_BL + bo);
                #pragma unroll
                for (int nj = 0; nj < 2; nj++) {
                    const uint32_t bh2[2] = { th[nj * 2], th[nj * 2 + 1] };
                    const uint32_t bl2[2] = { tl[nj * 2], tl[nj * 2 + 1] };
                    const int njj = pair * 2 + nj;
                    #pragma unroll
                    for (int mi = 0; mi < 2; mi++) {
                        mma16816f(acc_hh[mi][njj], ra_h[mi], bh2);
                        mma16816h(acc_cr[mi][njj], ra_h[mi], bl2);
                        mma16816h(acc_cr[mi][njj], ra_l[mi], bh2);
                    }
                }
            }
        }
    }

    // -------- epilogue --------
    const int rq = lane >> 2;
    const int cq = (lane & 3) * 2;
    #pragma unroll
    for (int mi = 0; mi < 2; mi++) {
        #pragma unroll
        for (int ni = 0; ni < 4; ni++) {
            const int mA = m0 + wm * 32 + mi * 16 + rq;
            const int mB = mA + 8;
            const int n  = n0 + wn * 32 + ni * 8 + cq;
            const float2 c01 = __half22float2(*(__half2*)&acc_cr[mi][ni][0]);
            const float2 c23 = __half22float2(*(__half2*)&acc_cr[mi][ni][1]);
            const float v0 = (acc_hh[mi][ni][0] + c01.x * INV_LO) * alpha;
            const float v1 = (acc_hh[mi][ni][1] + c01.y * INV_LO) * alpha;
            const float v2 = (acc_hh[mi][ni][2] + c23.x * INV_LO) * alpha;
            const float v3 = (acc_hh[mi][ni][3] + c23.y * INV_LO) * alpha;
            if (mode == 0) {
                float* Cf = (float*)C0 + (size_t)z * sC;
                *(float2*)(Cf + (size_t)mA * N + n) = make_float2(v0, v1);
                *(float2*)(Cf + (size_t)mB * N + n) = make_float2(v2, v3);
            } else if (mode == 1) {
                const __half h0 = __float2half_rn(v0), h1 = __float2half_rn(v1);
                const __half h2 = __float2half_rn(v2), h3 = __float2half_rn(v3);
                const __half l0 = __float2half_rn((v0 - __half2float(h0)) * LO_SCALE);
                const __half l1 = __float2half_rn((v1 - __half2float(h1)) * LO_SCALE);
                const __half l2 = __float2half_rn((v2 - __half2float(h2)) * LO_SCALE);
                const __half l3 = __float2half_rn((v3 - __half2float(h3)) * LO_SCALE);
                *(__half2*)((__half*)C0 + (size_t)mA * N + n) = __halves2half2(h0, h1);
                *(__half2*)((__half*)C0 + (size_t)mB * N + n) = __halves2half2(h2, h3);
                *(__half2*)((__half*)C1 + (size_t)mA * N + n) = __halves2half2(l0, l1);
                *(__half2*)((__half*)C1 + (size_t)mB * N + n) = __halves2half2(l2, l3);
            } else {
                // transposed store: C[b][e][n] with m -> (b, nn)
                const float vv[4] = { v0, v1, v2, v3 };
                #pragma unroll
                for (int e = 0; e < 4; e++) {
                    const int m = (e < 2) ? mA : mB;
                    const int nn2 = n + (e & 1);
                    const float val = vv[e];
                    const int bi = m >> 11;
                    const int mm = m & (N_ - 1);
                    const __half h = __float2half_rn(val);
                    const __half l = __float2half_rn((val - __half2float(h)) * LO_SCALE);
                    const size_t idx = ((size_t)bi * E_ + nn2) * N_ + mm;
                    ((__half*)C0)[idx] = h;
                    ((__half*)C1)[idx] = l;
                }
            }
        }
    }
}

// ---------------------------------------------------------------------------
// elementwise split: fp32 -> (fp16 hi, fp16 lo * 2048)
// ---------------------------------------------------------------------------
__device__ __forceinline__ void split_store4(__half* h, __half* l, size_t idx, float4 v) {
    const __half h0 = __float2half_rn(v.x);
    const __half h1 = __float2half_rn(v.y);
    const __half h2 = __float2half_rn(v.z);
    const __half h3 = __float2half_rn(v.w);
    const __half l0 = __float2half_rn((v.x - __half2float(h0)) * LO_SCALE);
    const __half l1 = __float2half_rn((v.y - __half2float(h1)) * LO_SCALE);
    const __half l2 = __float2half_rn((v.z - __half2float(h2)) * LO_SCALE);
    const __half l3 = __float2half_rn((v.w - __half2float(h3)) * LO_SCALE);
    __half2* hp = (__half2*)(h + idx);
    __half2* lp = (__half2*)(l + idx);
    hp[0] = __halves2half2(h0, h1);  hp[1] = __halves2half2(h2, h3);
    lp[0] = __halves2half2(l0, l1);  lp[1] = __halves2half2(l2, l3);
}

// one launch handles q, k, v (z = 0/1/2)
__global__ __launch_bounds__(256) void split_in(
    const float* __restrict__ q, const float* __restrict__ k, const float* __restrict__ v,
    __half* __restrict__ qh, __half* __restrict__ ql,
    __half* __restrict__ kh, __half* __restrict__ kl,
    __half* __restrict__ vh, __half* __restrict__ vl, long n4)
{
    const int zz = blockIdx.z;
    const float* x = (zz == 0) ? q : (zz == 1) ? k : v;
    __half* h = (zz == 0) ? qh : (zz == 1) ? kh : vh;
    __half* l = (zz == 0) ? ql : (zz == 1) ? kl : vl;
    for (long i = blockIdx.x * 256 + threadIdx.x; i < n4; i += (long)gridDim.x * 256) {
        float4 vv = ((const float4*)x)[i];
        split_store4(h, l, (size_t)i * 4, vv);
    }
}

__global__ __launch_bounds__(256) void split_w(
    const float* __restrict__ Wq, const float* __restrict__ Wk, const float* __restrict__ Wv,
    __half* __restrict__ qh, __half* __restrict__ ql,
    __half* __restrict__ kh, __half* __restrict__ kl,
    __half* __restrict__ vh, __half* __restrict__ vl, long n4)
{
    const int zz = blockIdx.z;
    const float* x = (zz == 0) ? Wq : (zz == 1) ? Wk : Wv;
    __half* h = (zz == 0) ? qh : (zz == 1) ? kh : vh;
    __half* l = (zz == 0) ? ql : (zz == 1) ? kl : vl;
    for (long i = blockIdx.x * 256 + threadIdx.x; i < n4; i += (long)gridDim.x * 256) {
        float4 vv = ((const float4*)x)[i];
        split_store4(h, l, (size_t)i * 4, vv);
    }
}

// ---------------------------------------------------------------------------
// fused softmax (in place, fp32) + fp16 hi/lo' emission. One block per row.
// ---------------------------------------------------------------------------
__global__ __launch_bounds__(256) void softmax_fused(
    float* __restrict__ attn, __half* __restrict__ ah, __half* __restrict__ al)
{
    const size_t row = blockIdx.x;
    float* p = attn + row * N_;
    const int t = threadIdx.x;
    __shared__ float red[8];

    float4 va = ((const float4*)p)[t];
    float4 vb = ((const float4*)p)[t + 256];

    float vmax = fmaxf(fmaxf(fmaxf(va.x, va.y), fmaxf(va.z, va.w)),
                       fmaxf(fmaxf(vb.x, vb.y), fmaxf(vb.z, vb.w)));
    #pragma unroll
    for (int o = 16; o > 0; o >>= 1) vmax = fmaxf(vmax, __shfl_xor_sync(0xFFFFFFFF, vmax, o));
    if ((t & 31) == 0) red[t >> 5] = vmax;
    __syncthreads();
    float m = fmaxf(fmaxf(fmaxf(red[0], red[1]), fmaxf(red[2], red[3])),
                    fmaxf(fmaxf(red[4], red[5]), fmaxf(red[6], red[7])));
    __syncthreads();

    va.x = __expf(va.x - m); va.y = __expf(va.y - m); va.z = __expf(va.z - m); va.w = __expf(va.w - m);
    vb.x = __expf(vb.x - m); vb.y = __expf(vb.y - m); vb.z = __expf(vb.z - m); vb.w = __expf(vb.w - m);

    float sum = va.x + va.y + va.z + va.w + vb.x + vb.y + vb.z + vb.w;
    #pragma unroll
    for (int o = 16; o > 0; o >>= 1) sum += __shfl_xor_sync(0xFFFFFFFF, sum, o);
    if ((t & 31) == 0) red[t >> 5] = sum;
    __syncthreads();
    const float inv = 1.0f / (red[0] + red[1] + red[2] + red[3] + red[4] + red[5] + red[6] + red[7]);

    va.x *= inv; va.y *= inv; va.z *= inv; va.w *= inv;
    vb.x *= inv; vb.y *= inv; vb.z *= inv; vb.w *= inv;

    ((float4*)p)[t]       = va;
    ((float4*)p)[t + 256] = vb;
    split_store4(ah, al, row * N_ + (size_t)t * 4,        va);
    split_store4(ah, al, row * N_ + 1024 + (size_t)t * 4, vb);
}

// ---------------------------------------------------------------------------
extern "C" void kernel_launch(void* const* d_in, const int* in_sizes, int n_in,
                              void* d_out, int out_size)
{
    const float* q  = (const float*)d_in[0];
    const float* k  = (const float*)d_in[1];
    const float* v  = (const float*)d_in[2];
    const float* Wq = (const float*)d_in[3];
    const float* Wk = (const float*)d_in[4];
    const float* Wv = (const float*)d_in[5];

    float* out  = (float*)d_out;                 // [B, N, E]
    float* attn = out + (long)B_ * N_ * E_;      // [B, N, N]

    cudaFuncSetAttribute(gemm3t, cudaFuncAttributeMaxDynamicSharedMemorySize, GEMM_SMEM_TOTAL);

    __half *qh, *ql, *kh, *kl, *vh, *vl;
    __half *Wqh, *Wql, *Wkh, *Wkl, *Wvh, *Wvl;
    __half *qph, *qpl, *kph, *kpl, *vpth, *vptl, *ah, *al;
    cudaGetSymbolAddress((void**)&qh, g_qh);   cudaGetSymbolAddress((void**)&ql, g_ql);
    cudaGetSymbolAddress((void**)&kh, g_kh);   cudaGetSymbolAddress((void**)&kl, g_kl);
    cudaGetSymbolAddress((void**)&vh, g_vh);   cudaGetSymbolAddress((void**)&vl, g_vl);
    cudaGetSymbolAddress((void**)&Wqh, g_Wqh); cudaGetSymbolAddress((void**)&Wql, g_Wql);
    cudaGetSymbolAddress((void**)&Wkh, g_Wkh); cudaGetSymbolAddress((void**)&Wkl, g_Wkl);
    cudaGetSymbolAddress((void**)&Wvh, g_Wvh); cudaGetSymbolAddress((void**)&Wvl, g_Wvl);
    cudaGetSymbolAddress((void**)&qph, g_qph); cudaGetSymbolAddress((void**)&qpl, g_qpl);
    cudaGetSymbolAddress((void**)&kph, g_kph); cudaGetSymbolAddress((void**)&kpl, g_kpl);
    cudaGetSymbolAddress((void**)&vpth, g_vpth); cudaGetSymbolAddress((void**)&vptl, g_vptl);
    cudaGetSymbolAddress((void**)&ah, g_ah);   cudaGetSymbolAddress((void**)&al, g_al);

    const float c_eq  = rsqrtf((float)D_);
    const float scale = rsqrtf((float)E_);

    // 1-2) splits (2 launches)
    {
        dim3 gi(2048, 1, 3);
        split_in<<<gi, 256>>>(q, k, v, qh, ql, kh, kl, vh, vl, QKV_ELEMS / 4);
        dim3 gw(256, 1, 3);
        split_w<<<gw, 256>>>(Wq, Wk, Wv, Wqh, Wql, Wkh, Wkl, Wvh, Wvl, W_ELEMS / 4);
    }

    // 3-5) projections: [16384,512] @ W^T, alpha=c_eq
    {
        dim3 grid(E_ / 128, (B_ * N_) / 128, 1);
        gemm3t<<<grid, 512, GEMM_SMEM_TOTAL>>>(qh, ql, Wqh, Wql, B_ * N_, E_, D_,
                                               0, 0, 0, c_eq, 1, qph, qpl);
        gemm3t<<<grid, 512, GEMM_SMEM_TOTAL>>>(kh, kl, Wkh, Wkl, B_ * N_, E_, D_,
                                               0, 0, 0, c_eq, 1, kph, kpl);
        gemm3t<<<grid, 512, GEMM_SMEM_TOTAL>>>(vh, vl, Wvh, Wvl, B_ * N_, E_, D_,
                                               0, 0, 0, c_eq, 2, vpth, vptl);
    }

    // 6) dots = qp @ kp^T * scale -> attn region (fp32), batched  [ncu-captured launch]
    {
        dim3 grid(N_ / 128, N_ / 128, B_);
        gemm3t<<<grid, 512, GEMM_SMEM_TOTAL>>>(qph, qpl, kph, kpl, N_, N_, E_,
                                               (long)N_ * E_, (long)N_ * E_, (long)N_ * N_,
                                               scale, 0, attn, nullptr);
    }

    // 7) softmax (in place) + fp16 hi/lo' split of attn
    softmax_fused<<<B_ * N_, 256>>>(attn, ah, al);

    // 8) out = attn @ vp (vp^T stored [b][e][n], K=N_=2048 contiguous)
    {
        dim3 grid(E_ / 128, N_ / 128, B_);
        gemm3t<<<grid, 512, GEMM_SMEM_TOTAL>>>(ah, al, vpth, vptl, N_, E_, N_,
                                               (long)N_ * N_, (long)E_ * N_, (long)N_ * E_,
                                               1.0f, 0, out, nullptr);
    }
}

// round 7
// speedup vs baseline: 1.7743x; 1.1169x over previous
#include <cuda_runtime.h>
#include <cuda_fp16.h>
#include <cstdint>
#include <math.h>

// Problem constants
#define B_ 8
#define N_ 2048
#define D_ 512
#define E_ 512

static constexpr long QKV_ELEMS  = (long)B_ * N_ * D_;   // 8,388,608
static constexpr long W_ELEMS    = (long)E_ * D_;        // 262,144
static constexpr long ATTN_ELEMS = (long)B_ * N_ * N_;   // 33,554,432

// ---------------- scratch (static device arrays; allocation-guard safe) ----
__device__ __half g_qh[QKV_ELEMS],  g_ql[QKV_ELEMS];
__device__ __half g_kh[QKV_ELEMS],  g_kl[QKV_ELEMS];
__device__ __half g_vh[QKV_ELEMS],  g_vl[QKV_ELEMS];
__device__ __half g_Wqh[W_ELEMS],   g_Wql[W_ELEMS];
__device__ __half g_Wkh[W_ELEMS],   g_Wkl[W_ELEMS];
__device__ __half g_Wvh[W_ELEMS],   g_Wvl[W_ELEMS];
__device__ __half g_qph[QKV_ELEMS], g_qpl[QKV_ELEMS];
__device__ __half g_kph[QKV_ELEMS], g_kpl[QKV_ELEMS];
__device__ __half g_vpth[QKV_ELEMS], g_vptl[QKV_ELEMS];   // transposed [b][e][n]
__device__ __half g_ah[ATTN_ELEMS], g_al[ATTN_ELEMS];

// ---------------- PTX helpers ----------------------------------------------
__device__ __forceinline__ uint32_t smem_to_u32(const void* p) {
    uint32_t a;
    asm("{ .reg .u64 t; cvta.to.shared.u64 t, %1; cvt.u32.u64 %0, t; }" : "=r"(a) : "l"(p));
    return a;
}

#define CP_ASYNC16(smem_u32, gptr) \
    asm volatile("cp.async.cg.shared.global [%0], [%1], 16;" :: "r"(smem_u32), "l"(gptr) : "memory")
#define CP_ASYNC_COMMIT() asm volatile("cp.async.commit_group;" ::: "memory")
#define CP_ASYNC_WAIT1()  asm volatile("cp.async.wait_group 1;" ::: "memory")

__device__ __forceinline__ void ldsm_x4(uint32_t* r, uint32_t addr) {
    asm volatile("ldmatrix.sync.aligned.m8n8.x4.shared.b16 {%0,%1,%2,%3}, [%4];"
        : "=r"(r[0]), "=r"(r[1]), "=r"(r[2]), "=r"(r[3]) : "r"(addr));
}

__device__ __forceinline__ void mma16816(float* c, const uint32_t* a, const uint32_t* b) {
    asm volatile(
        "mma.sync.aligned.m16n8k16.row.col.f32.f16.f16.f32 "
        "{%0,%1,%2,%3}, {%4,%5,%6,%7}, {%8,%9}, {%0,%1,%2,%3};"
        : "+f"(c[0]), "+f"(c[1]), "+f"(c[2]), "+f"(c[3])
        : "r"(a[0]), "r"(a[1]), "r"(a[2]), "r"(a[3]), "r"(b[0]), "r"(b[1]));
}

// ---------------------------------------------------------------------------
// 3-term fp16-split GEMM:  C = alpha * (Ah+Al) @ (Bh+Bl)^T  (drop Al*Bl)
// A: [M,K] row-major (K contig), B: [N,K] row-major (K contig)
// mode 0: C0 fp32 [M,N] (+ z*sC);  mode 1: C0/C1 fp16 hi/lo [M,N];
// mode 2: C0/C1 fp16 hi/lo transposed as [b][E_][N_] (v-projection only).
// Block tile 128x256, BK=32, 8 warps (warp tile 64x64), 3-stage cp.async ring,
// B-fragment one-pair-ahead register prefetch.
// ---------------------------------------------------------------------------
#define BKH 32                              // K halves per slab
#define ROWH 40                             // padded row length in halves
#define ROWB 80                             // row bytes
#define A_TILE_B (128 * ROWB)               // 10240
#define B_TILE_B (256 * ROWB)               // 20480
#define STAGE_B (2 * A_TILE_B + 2 * B_TILE_B)   // 61440: Ah, Al, Bh, Bl
#define OFF_AL (A_TILE_B)
#define OFF_BH (2 * A_TILE_B)
#define OFF_BL (2 * A_TILE_B + B_TILE_B)
#define NSTAGE 3
#define GEMM_SMEM_TOTAL (NSTAGE * STAGE_B)  // 184320

__global__ __launch_bounds__(256, 1) void gemm3t(
    const __half* __restrict__ Ah, const __half* __restrict__ Al,
    const __half* __restrict__ Bh, const __half* __restrict__ Bl,
    int M, int N, int K,
    long sA, long sB, long sC,
    float alpha, int mode,
    void* __restrict__ C0, void* __restrict__ C1)
{
    extern __shared__ char smem[];
    const uint32_t smem_base = smem_to_u32(smem);
    const int tid  = threadIdx.x;
    const int wid  = tid >> 5;
    const int lane = tid & 31;
    const int wm = wid & 1;        // 2 warps along M (64 rows each)
    const int wn = wid >> 1;       // 4 warps along N (64 cols each)
    const int z = blockIdx.z;

    Ah += (long)z * sA;  Al += (long)z * sA;
    Bh += (long)z * sB;  Bl += (long)z * sB;

    const int m0 = blockIdx.y * 128;
    const int n0 = blockIdx.x * 256;

    float acc[4][8][4];
    #pragma unroll
    for (int i = 0; i < 4; i++)
        #pragma unroll
        for (int j = 0; j < 8; j++)
            #pragma unroll
            for (int c = 0; c < 4; c++) acc[i][j][c] = 0.0f;

    const int nslab = K / BKH;
    const int lrow = tid >> 2;
    const int lch  = tid & 3;

    // -------- async slab loader: 12 cp.async per thread --------
    auto load_slab = [&](int s) {
        const long koff = (long)s * BKH + lch * 8;
        const uint32_t st = smem_base + (uint32_t)(s % NSTAGE) * STAGE_B;
        const uint32_t so = (uint32_t)(lrow * ROWB + lch * 16);
        #pragma unroll
        for (int i = 0; i < 2; i++) {      // A: 128 rows
            const int r = lrow + 64 * i;
            const long g = (long)(m0 + r) * K + koff;
            CP_ASYNC16(st +          so + i * (64 * ROWB), Ah + g);
            CP_ASYNC16(st + OFF_AL + so + i * (64 * ROWB), Al + g);
        }
        #pragma unroll
        for (int i = 0; i < 4; i++) {      // B: 256 rows
            const int r = lrow + 64 * i;
            const long g = (long)(n0 + r) * K + koff;
            CP_ASYNC16(st + OFF_BH + so + i * (64 * ROWB), Bh + g);
            CP_ASYNC16(st + OFF_BL + so + i * (64 * ROWB), Bl + g);
        }
    };

    load_slab(0); CP_ASYNC_COMMIT();
    if (nslab > 1) load_slab(1);
    CP_ASYNC_COMMIT();

    const int am = lane & 15;
    const int ac = (lane >> 4) << 3;
    const int bn = ((lane >> 4) << 3) + (lane & 7);
    const int bc = ((lane >> 3) & 1) << 3;

    for (int s = 0; s < nslab; s++) {
        CP_ASYNC_WAIT1();          // slab s resident (only s+1 may be pending)
        __syncthreads();           // all warps past previous consume + see data

        const uint32_t st = smem_base + (uint32_t)(s % NSTAGE) * STAGE_B;
        #pragma unroll
        for (int k16 = 0; k16 < 2; k16++) {
            // ---- A fragments (hi/lo): 8 ldsm.x4 ----
            uint32_t ra_h[4][4], ra_l[4][4];
            #pragma unroll
            for (int mi = 0; mi < 4; mi++) {
                const uint32_t ao =
                    (uint32_t)((wm * 64 + mi * 16 + am) * ROWH + k16 * 16 + ac) * 2;
                ldsm_x4(ra_h[mi], st + ao);
                ldsm_x4(ra_l[mi], st + OFF_AL + ao);
            }
            // ---- B pair 0 prologue ----
            uint32_t th[2][4], tl[2][4];
            const uint32_t bbase =
                (uint32_t)((wn * 64 + bn) * ROWH + k16 * 16 + bc) * 2;
            ldsm_x4(th[0], st + OFF_BH + bbase);
            ldsm_x4(tl[0], st + OFF_BL + bbase);

            // issue next-next slab's loads behind the prologue ldsm latency
            if (k16 == 0) {
                if (s + 2 < nslab) load_slab(s + 2);
                CP_ASYNC_COMMIT();
            }

            // ---- pair loop with one-pair-ahead B prefetch ----
            #pragma unroll
            for (int pair = 0; pair < 4; pair++) {
                const int cur = pair & 1;
                if (pair < 3) {
                    const uint32_t bo = bbase + (uint32_t)((pair + 1) * 16 * ROWH) * 2;
                    ldsm_x4(th[cur ^ 1], st + OFF_BH + bo);
                    ldsm_x4(tl[cur ^ 1], st + OFF_BL + bo);
                }
                #pragma unroll
                for (int nj = 0; nj < 2; nj++) {
                    const uint32_t bh2[2] = { th[cur][nj * 2], th[cur][nj * 2 + 1] };
                    const uint32_t bl2[2] = { tl[cur][nj * 2], tl[cur][nj * 2 + 1] };
                    #pragma unroll
                    for (int mi = 0; mi < 4; mi++) {
                        float* a = acc[mi][pair * 2 + nj];
                        mma16816(a, ra_h[mi], bh2);
                        mma16816(a, ra_h[mi], bl2);
                        mma16816(a, ra_l[mi], bh2);
                    }
                }
            }
        }
    }

    // -------- epilogue (register accumulators -> global) --------
    const int rq = lane >> 2;             // 0..7
    const int cq = (lane & 3) * 2;
    #pragma unroll
    for (int mi = 0; mi < 4; mi++) {
        #pragma unroll
        for (int ni = 0; ni < 8; ni++) {
            const int mA = m0 + wm * 64 + mi * 16 + rq;
            const int mB = mA + 8;
            const int n  = n0 + wn * 64 + ni * 8 + cq;
            const float v0 = acc[mi][ni][0] * alpha;
            const float v1 = acc[mi][ni][1] * alpha;
            const float v2 = acc[mi][ni][2] * alpha;
            const float v3 = acc[mi][ni][3] * alpha;
            if (mode == 0) {
                float* Cf = (float*)C0 + (size_t)z * sC;
                *(float2*)(Cf + (size_t)mA * N + n) = make_float2(v0, v1);
                *(float2*)(Cf + (size_t)mB * N + n) = make_float2(v2, v3);
            } else if (mode == 1) {
                __half h0 = __float2half_rn(v0), h1 = __float2half_rn(v1);
                __half h2 = __float2half_rn(v2), h3 = __float2half_rn(v3);
                __half l0 = __float2half_rn(v0 - __half2float(h0));
                __half l1 = __float2half_rn(v1 - __half2float(h1));
                __half l2 = __float2half_rn(v2 - __half2float(h2));
                __half l3 = __float2half_rn(v3 - __half2float(h3));
                *(__half2*)((__half*)C0 + (size_t)mA * N + n) = __halves2half2(h0, h1);
                *(__half2*)((__half*)C0 + (size_t)mB * N + n) = __halves2half2(h2, h3);
                *(__half2*)((__half*)C1 + (size_t)mA * N + n) = __halves2half2(l0, l1);
                *(__half2*)((__half*)C1 + (size_t)mB * N + n) = __halves2half2(l2, l3);
            } else {
                // transposed store: C[b][e][n] with m -> (b, nn)
                const float vv[4] = { v0, v1, v2, v3 };
                #pragma unroll
                for (int e = 0; e < 4; e++) {
                    const int m = (e < 2) ? mA : mB;
                    const int nn2 = n + (e & 1);
                    const float val = vv[e];
                    const int bi = m >> 11;
                    const int mm = m & (N_ - 1);
                    const __half h = __float2half_rn(val);
                    const __half l = __float2half_rn(val - __half2float(h));
                    const size_t idx = ((size_t)bi * E_ + nn2) * N_ + mm;
                    ((__half*)C0)[idx] = h;
                    ((__half*)C1)[idx] = l;
                }
            }
        }
    }
}

// ---------------------------------------------------------------------------
// elementwise split: fp32 -> (fp16 hi, fp16 lo)
// ---------------------------------------------------------------------------
__device__ __forceinline__ void split_store4(__half* h, __half* l, size_t idx, float4 v) {
    const __half h0 = __float2half_rn(v.x);
    const __half h1 = __float2half_rn(v.y);
    const __half h2 = __float2half_rn(v.z);
    const __half h3 = __float2half_rn(v.w);
    const __half l0 = __float2half_rn(v.x - __half2float(h0));
    const __half l1 = __float2half_rn(v.y - __half2float(h1));
    const __half l2 = __float2half_rn(v.z - __half2float(h2));
    const __half l3 = __float2half_rn(v.w - __half2float(h3));
    __half2* hp = (__half2*)(h + idx);
    __half2* lp = (__half2*)(l + idx);
    hp[0] = __halves2half2(h0, h1);  hp[1] = __halves2half2(h2, h3);
    lp[0] = __halves2half2(l0, l1);  lp[1] = __halves2half2(l2, l3);
}

// one launch handles q, k, v (z = 0/1/2)
__global__ __launch_bounds__(256) void split_in(
    const float* __restrict__ q, const float* __restrict__ k, const float* __restrict__ v,
    __half* __restrict__ qh, __half* __restrict__ ql,
    __half* __restrict__ kh, __half* __restrict__ kl,
    __half* __restrict__ vh, __half* __restrict__ vl, long n4)
{
    const int zz = blockIdx.z;
    const float* x = (zz == 0) ? q : (zz == 1) ? k : v;
    __half* h = (zz == 0) ? qh : (zz == 1) ? kh : vh;
    __half* l = (zz == 0) ? ql : (zz == 1) ? kl : vl;
    for (long i = blockIdx.x * 256 + threadIdx.x; i < n4; i += (long)gridDim.x * 256) {
        float4 vv = ((const float4*)x)[i];
        split_store4(h, l, (size_t)i * 4, vv);
    }
}

__global__ __launch_bounds__(256) void split_w(
    const float* __restrict__ Wq, const float* __restrict__ Wk, const float* __restrict__ Wv,
    __half* __restrict__ qh, __half* __restrict__ ql,
    __half* __restrict__ kh, __half* __restrict__ kl,
    __half* __restrict__ vh, __half* __restrict__ vl, long n4)
{
    const int zz = blockIdx.z;
    const float* x = (zz == 0) ? Wq : (zz == 1) ? Wk : Wv;
    __half* h = (zz == 0) ? qh : (zz == 1) ? kh : vh;
    __half* l = (zz == 0) ? ql : (zz == 1) ? kl : vl;
    for (long i = blockIdx.x * 256 + threadIdx.x; i < n4; i += (long)gridDim.x * 256) {
        float4 vv = ((const float4*)x)[i];
        split_store4(h, l, (size_t)i * 4, vv);
    }
}

// ---------------------------------------------------------------------------
// fused softmax (in place, fp32) + fp16 hi/lo emission. One block per row.
// ---------------------------------------------------------------------------
__global__ __launch_bounds__(256) void softmax_fused(
    float* __restrict__ attn, __half* __restrict__ ah, __half* __restrict__ al)
{
    const size_t row = blockIdx.x;
    float* p = attn + row * N_;
    const int t = threadIdx.x;
    __shared__ float red[8];

    float4 va = ((const float4*)p)[t];
    float4 vb = ((const float4*)p)[t + 256];

    float vmax = fmaxf(fmaxf(fmaxf(va.x, va.y), fmaxf(va.z, va.w)),
                       fmaxf(fmaxf(vb.x, vb.y), fmaxf(vb.z, vb.w)));
    #pragma unroll
    for (int o = 16; o > 0; o >>= 1) vmax = fmaxf(vmax, __shfl_xor_sync(0xFFFFFFFF, vmax, o));
    if ((t & 31) == 0) red[t >> 5] = vmax;
    __syncthreads();
    float m = fmaxf(fmaxf(fmaxf(red[0], red[1]), fmaxf(red[2], red[3])),
                    fmaxf(fmaxf(red[4], red[5]), fmaxf(red[6], red[7])));
    __syncthreads();

    va.x = __expf(va.x - m); va.y = __expf(va.y - m); va.z = __expf(va.z - m); va.w = __expf(va.w - m);
    vb.x = __expf(vb.x - m); vb.y = __expf(vb.y - m); vb.z = __expf(vb.z - m); vb.w = __expf(vb.w - m);

    float sum = va.x + va.y + va.z + va.w + vb.x + vb.y + vb.z + vb.w;
    #pragma unroll
    for (int o = 16; o > 0; o >>= 1) sum += __shfl_xor_sync(0xFFFFFFFF, sum, o);
    if ((t & 31) == 0) red[t >> 5] = sum;
    __syncthreads();
    const float inv = 1.0f / (red[0] + red[1] + red[2] + red[3] + red[4] + red[5] + red[6] + red[7]);

    va.x *= inv; va.y *= inv; va.z *= inv; va.w *= inv;
    vb.x *= inv; vb.y *= inv; vb.z *= inv; vb.w *= inv;

    ((float4*)p)[t]       = va;
    ((float4*)p)[t + 256] = vb;
    split_store4(ah, al, row * N_ + (size_t)t * 4,        va);
    split_store4(ah, al, row * N_ + 1024 + (size_t)t * 4, vb);
}

// ---------------------------------------------------------------------------
extern "C" void kernel_launch(void* const* d_in, const int* in_sizes, int n_in,
                              void* d_out, int out_size)
{
    const float* q  = (const float*)d_in[0];
    const float* k  = (const float*)d_in[1];
    const float* v  = (const float*)d_in[2];
    const float* Wq = (const float*)d_in[3];
    const float* Wk = (const float*)d_in[4];
    const float* Wv = (const float*)d_in[5];

    float* out  = (float*)d_out;                 // [B, N, E]
    float* attn = out + (long)B_ * N_ * E_;      // [B, N, N]

    cudaFuncSetAttribute(gemm3t, cudaFuncAttributeMaxDynamicSharedMemorySize, GEMM_SMEM_TOTAL);

    __half *qh, *ql, *kh, *kl, *vh, *vl;
    __half *Wqh, *Wql, *Wkh, *Wkl, *Wvh, *Wvl;
    __half *qph, *qpl, *kph, *kpl, *vpth, *vptl, *ah, *al;
    cudaGetSymbolAddress((void**)&qh, g_qh);   cudaGetSymbolAddress((void**)&ql, g_ql);
    cudaGetSymbolAddress((void**)&kh, g_kh);   cudaGetSymbolAddress((void**)&kl, g_kl);
    cudaGetSymbolAddress((void**)&vh, g_vh);   cudaGetSymbolAddress((void**)&vl, g_vl);
    cudaGetSymbolAddress((void**)&Wqh, g_Wqh); cudaGetSymbolAddress((void**)&Wql, g_Wql);
    cudaGetSymbolAddress((void**)&Wkh, g_Wkh); cudaGetSymbolAddress((void**)&Wkl, g_Wkl);
    cudaGetSymbolAddress((void**)&Wvh, g_Wvh); cudaGetSymbolAddress((void**)&Wvl, g_Wvl);
    cudaGetSymbolAddress((void**)&qph, g_qph); cudaGetSymbolAddress((void**)&qpl, g_qpl);
    cudaGetSymbolAddress((void**)&kph, g_kph); cudaGetSymbolAddress((void**)&kpl, g_kpl);
    cudaGetSymbolAddress((void**)&vpth, g_vpth); cudaGetSymbolAddress((void**)&vptl, g_vptl);
    cudaGetSymbolAddress((void**)&ah, g_ah);   cudaGetSymbolAddress((void**)&al, g_al);

    const float c_eq  = rsqrtf((float)D_);
    const float scale = rsqrtf((float)E_);

    // 1-2) splits (2 launches)
    {
        dim3 gi(2048, 1, 3);
        split_in<<<gi, 256>>>(q, k, v, qh, ql, kh, kl, vh, vl, QKV_ELEMS / 4);
        dim3 gw(256, 1, 3);
        split_w<<<gw, 256>>>(Wq, Wk, Wv, Wqh, Wql, Wkh, Wkl, Wvh, Wvl, W_ELEMS / 4);
    }

    // 3-5) projections: [16384,512] @ W^T, alpha=c_eq
    {
        dim3 grid(E_ / 256, (B_ * N_) / 128, 1);
        gemm3t<<<grid, 256, GEMM_SMEM_TOTAL>>>(qh, ql, Wqh, Wql, B_ * N_, E_, D_,
                                               0, 0, 0, c_eq, 1, qph, qpl);
        gemm3t<<<grid, 256, GEMM_SMEM_TOTAL>>>(kh, kl, Wkh, Wkl, B_ * N_, E_, D_,
                                               0, 0, 0, c_eq, 1, kph, kpl);
        gemm3t<<<grid, 256, GEMM_SMEM_TOTAL>>>(vh, vl, Wvh, Wvl, B_ * N_, E_, D_,
                                               0, 0, 0, c_eq, 2, vpth, vptl);
    }

    // 6) dots = qp @ kp^T * scale -> attn region (fp32), batched
    {
        dim3 grid(N_ / 256, N_ / 128, B_);
        gemm3t<<<grid, 256, GEMM_SMEM_TOTAL>>>(qph, qpl, kph, kpl, N_, N_, E_,
                                               (long)N_ * E_, (long)N_ * E_, (long)N_ * N_,
                                               scale, 0, attn, nullptr);
    }

    // 7) softmax (in place) + fp16 hi/lo split of attn
    softmax_fused<<<B_ * N_, 256>>>(attn, ah, al);

    // 8) out = attn @ vp (vp^T stored [b][e][n], K=N_=2048 contiguous)
    {
        dim3 grid(E_ / 256, N_ / 128, B_);
        gemm3t<<<grid, 256, GEMM_SMEM_TOTAL>>>(ah, al, vpth, vptl, N_, E_, N_,
                                               (long)N_ * N_, (long)E_ * N_, (long)N_ * E_,
                                               1.0f, 0, out, nullptr);
    }
}

// round 8
// speedup vs baseline: 2.4740x; 1.3944x over previous
#include <cuda_runtime.h>
#include <cuda_fp16.h>
#include <cstdint>
#include <math.h>

// Problem constants
#define B_ 8
#define N_ 2048
#define D_ 512
#define E_ 512

static constexpr long QKV_ELEMS  = (long)B_ * N_ * D_;   // 8,388,608
static constexpr long W_ELEMS    = (long)E_ * D_;        // 262,144
static constexpr long ATTN_ELEMS = (long)B_ * N_ * N_;   // 33,554,432

// ---------------- scratch (static device arrays; allocation-guard safe) ----
__device__ __half g_q16[QKV_ELEMS], g_k16[QKV_ELEMS], g_v16[QKV_ELEMS];
__device__ __half g_Wqh[W_ELEMS],   g_Wql[W_ELEMS];
__device__ __half g_Wkh[W_ELEMS],   g_Wkl[W_ELEMS];
__device__ __half g_Wvh[W_ELEMS],   g_Wvl[W_ELEMS];
__device__ __half g_qph[QKV_ELEMS];                       // q-proj: hi only
__device__ __half g_kph[QKV_ELEMS], g_kpl[QKV_ELEMS];
__device__ __half g_vpth[QKV_ELEMS], g_vptl[QKV_ELEMS];   // transposed [b][e][n]
__device__ __half g_ah[ATTN_ELEMS];                       // attn: hi only

// ---------------- PTX helpers ----------------------------------------------
__device__ __forceinline__ uint32_t smem_to_u32(const void* p) {
    uint32_t a;
    asm("{ .reg .u64 t; cvta.to.shared.u64 t, %1; cvt.u32.u64 %0, t; }" : "=r"(a) : "l"(p));
    return a;
}

#define CP_ASYNC16(smem_u32, gptr) \
    asm volatile("cp.async.cg.shared.global [%0], [%1], 16;" :: "r"(smem_u32), "l"(gptr) : "memory")
#define CP_ASYNC_COMMIT() asm volatile("cp.async.commit_group;" ::: "memory")
#define CP_ASYNC_WAIT1()  asm volatile("cp.async.wait_group 1;" ::: "memory")

__device__ __forceinline__ void ldsm_x4(uint32_t* r, uint32_t addr) {
    asm volatile("ldmatrix.sync.aligned.m8n8.x4.shared.b16 {%0,%1,%2,%3}, [%4];"
        : "=r"(r[0]), "=r"(r[1]), "=r"(r[2]), "=r"(r[3]) : "r"(addr));
}

__device__ __forceinline__ void mma16816(float* c, const uint32_t* a, const uint32_t* b) {
    asm volatile(
        "mma.sync.aligned.m16n8k16.row.col.f32.f16.f16.f32 "
        "{%0,%1,%2,%3}, {%4,%5,%6,%7}, {%8,%9}, {%0,%1,%2,%3};"
        : "+f"(c[0]), "+f"(c[1]), "+f"(c[2]), "+f"(c[3])
        : "r"(a[0]), "r"(a[1]), "r"(a[2]), "r"(a[3]), "r"(b[0]), "r"(b[1]));
}

// ---------------------------------------------------------------------------
// 2-product asymmetric-split GEMM:  C = alpha * A @ (Bh+Bl)^T
// A: [M,K] fp16 row-major K-contig; Bh/Bl: [N,K] fp16 hi/lo limbs.
// mode 0: C0 fp32 [M,N] (+ z*sC);  mode 1: C0/C1 fp16 hi/lo [M,N];
// mode 2: C0/C1 fp16 hi/lo transposed [b][E_][N_];  mode 4: C0 fp16 hi only.
// Block tile 128x256, BK=32, 8 warps (warp tile 64x64), 3-stage cp.async ring,
// B-fragment one-pair-ahead register prefetch.
// ---------------------------------------------------------------------------
#define BKH 32                              // K halves per slab
#define ROWH 40                             // padded row length in halves
#define ROWB 80                             // row bytes
#define A_TILE_B (128 * ROWB)               // 10240
#define B_TILE_B (256 * ROWB)               // 20480
#define STAGE_B (A_TILE_B + 2 * B_TILE_B)   // 51200: A, Bh, Bl
#define OFF_BH (A_TILE_B)
#define OFF_BL (A_TILE_B + B_TILE_B)
#define NSTAGE 3
#define GEMM_SMEM_TOTAL (NSTAGE * STAGE_B)  // 153600

__global__ __launch_bounds__(256, 1) void gemm2t(
    const __half* __restrict__ A,
    const __half* __restrict__ Bh, const __half* __restrict__ Bl,
    int M, int N, int K,
    long sA, long sB, long sC,
    float alpha, int mode,
    void* __restrict__ C0, void* __restrict__ C1)
{
    extern __shared__ char smem[];
    const uint32_t smem_base = smem_to_u32(smem);
    const int tid  = threadIdx.x;
    const int wid  = tid >> 5;
    const int lane = tid & 31;
    const int wm = wid & 1;        // 2 warps along M (64 rows each)
    const int wn = wid >> 1;       // 4 warps along N (64 cols each)
    const int z = blockIdx.z;

    A  += (long)z * sA;
    Bh += (long)z * sB;  Bl += (long)z * sB;

    const int m0 = blockIdx.y * 128;
    const int n0 = blockIdx.x * 256;

    float acc[4][8][4];
    #pragma unroll
    for (int i = 0; i < 4; i++)
        #pragma unroll
        for (int j = 0; j < 8; j++)
            #pragma unroll
            for (int c = 0; c < 4; c++) acc[i][j][c] = 0.0f;

    const int nslab = K / BKH;
    const int lrow = tid >> 2;
    const int lch  = tid & 3;

    // -------- async slab loader: 10 cp.async per thread --------
    auto load_slab = [&](int s) {
        const long koff = (long)s * BKH + lch * 8;
        const uint32_t st = smem_base + (uint32_t)(s % NSTAGE) * STAGE_B;
        const uint32_t so = (uint32_t)(lrow * ROWB + lch * 16);
        #pragma unroll
        for (int i = 0; i < 2; i++) {      // A: 128 rows
            const int r = lrow + 64 * i;
            const long g = (long)(m0 + r) * K + koff;
            CP_ASYNC16(st + so + i * (64 * ROWB), A + g);
        }
        #pragma unroll
        for (int i = 0; i < 4; i++) {      // B: 256 rows
            const int r = lrow + 64 * i;
            const long g = (long)(n0 + r) * K + koff;
            CP_ASYNC16(st + OFF_BH + so + i * (64 * ROWB), Bh + g);
            CP_ASYNC16(st + OFF_BL + so + i * (64 * ROWB), Bl + g);
        }
    };

    load_slab(0); CP_ASYNC_COMMIT();
    if (nslab > 1) load_slab(1);
    CP_ASYNC_COMMIT();

    const int am = lane & 15;
    const int ac = (lane >> 4) << 3;
    const int bn = ((lane >> 4) << 3) + (lane & 7);
    const int bc = ((lane >> 3) & 1) << 3;

    for (int s = 0; s < nslab; s++) {
        CP_ASYNC_WAIT1();          // slab s resident (only s+1 may be pending)
        __syncthreads();

        const uint32_t st = smem_base + (uint32_t)(s % NSTAGE) * STAGE_B;
        #pragma unroll
        for (int k16 = 0; k16 < 2; k16++) {
            // ---- A fragments: 4 ldsm.x4 ----
            uint32_t ra[4][4];
            #pragma unroll
            for (int mi = 0; mi < 4; mi++) {
                const uint32_t ao =
                    (uint32_t)((wm * 64 + mi * 16 + am) * ROWH + k16 * 16 + ac) * 2;
                ldsm_x4(ra[mi], st + ao);
            }
            // ---- B pair 0 prologue ----
            uint32_t th[2][4], tl[2][4];
            const uint32_t bbase =
                (uint32_t)((wn * 64 + bn) * ROWH + k16 * 16 + bc) * 2;
            ldsm_x4(th[0], st + OFF_BH + bbase);
            ldsm_x4(tl[0], st + OFF_BL + bbase);

            // issue next-next slab's loads behind the prologue ldsm latency
            if (k16 == 0) {
                if (s + 2 < nslab) load_slab(s + 2);
                CP_ASYNC_COMMIT();
            }

            // ---- pair loop with one-pair-ahead B prefetch ----
            #pragma unroll
            for (int pair = 0; pair < 4; pair++) {
                const int cur = pair & 1;
                if (pair < 3) {
                    const uint32_t bo = bbase + (uint32_t)((pair + 1) * 16 * ROWH) * 2;
                    ldsm_x4(th[cur ^ 1], st + OFF_BH + bo);
                    ldsm_x4(tl[cur ^ 1], st + OFF_BL + bo);
                }
                #pragma unroll
                for (int nj = 0; nj < 2; nj++) {
                    const uint32_t bh2[2] = { th[cur][nj * 2], th[cur][nj * 2 + 1] };
                    const uint32_t bl2[2] = { tl[cur][nj * 2], tl[cur][nj * 2 + 1] };
                    #pragma unroll
                    for (int mi = 0; mi < 4; mi++) {
                        float* a = acc[mi][pair * 2 + nj];
                        mma16816(a, ra[mi], bh2);
                        mma16816(a, ra[mi], bl2);
                    }
                }
            }
        }
    }

    // -------- epilogue (register accumulators -> global) --------
    const int rq = lane >> 2;             // 0..7
    const int cq = (lane & 3) * 2;
    #pragma unroll
    for (int mi = 0; mi < 4; mi++) {
        #pragma unroll
        for (int ni = 0; ni < 8; ni++) {
            const int mA = m0 + wm * 64 + mi * 16 + rq;
            const int mB = mA + 8;
            const int n  = n0 + wn * 64 + ni * 8 + cq;
            const float v0 = acc[mi][ni][0] * alpha;
            const float v1 = acc[mi][ni][1] * alpha;
            const float v2 = acc[mi][ni][2] * alpha;
            const float v3 = acc[mi][ni][3] * alpha;
            if (mode == 0) {
                float* Cf = (float*)C0 + (size_t)z * sC;
                *(float2*)(Cf + (size_t)mA * N + n) = make_float2(v0, v1);
                *(float2*)(Cf + (size_t)mB * N + n) = make_float2(v2, v3);
            } else if (mode == 4) {
                *(__half2*)((__half*)C0 + (size_t)mA * N + n) =
                    __halves2half2(__float2half_rn(v0), __float2half_rn(v1));
                *(__half2*)((__half*)C0 + (size_t)mB * N + n) =
                    __halves2half2(__float2half_rn(v2), __float2half_rn(v3));
            } else if (mode == 1) {
                __half h0 = __float2half_rn(v0), h1 = __float2half_rn(v1);
                __half h2 = __float2half_rn(v2), h3 = __float2half_rn(v3);
                __half l0 = __float2half_rn(v0 - __half2float(h0));
                __half l1 = __float2half_rn(v1 - __half2float(h1));
                __half l2 = __float2half_rn(v2 - __half2float(h2));
                __half l3 = __float2half_rn(v3 - __half2float(h3));
                *(__half2*)((__half*)C0 + (size_t)mA * N + n) = __halves2half2(h0, h1);
                *(__half2*)((__half*)C0 + (size_t)mB * N + n) = __halves2half2(h2, h3);
                *(__half2*)((__half*)C1 + (size_t)mA * N + n) = __halves2half2(l0, l1);
                *(__half2*)((__half*)C1 + (size_t)mB * N + n) = __halves2half2(l2, l3);
            } else {
                // transposed store: C[b][e][n] with m -> (b, nn)
                const float vv[4] = { v0, v1, v2, v3 };
                #pragma unroll
                for (int e = 0; e < 4; e++) {
                    const int m = (e < 2) ? mA : mB;
                    const int nn2 = n + (e & 1);
                    const float val = vv[e];
                    const int bi = m >> 11;
                    const int mm = m & (N_ - 1);
                    const __half h = __float2half_rn(val);
                    const __half l = __float2half_rn(val - __half2float(h));
                    const size_t idx = ((size_t)bi * E_ + nn2) * N_ + mm;
                    ((__half*)C0)[idx] = h;
                    ((__half*)C1)[idx] = l;
                }
            }
        }
    }
}

// ---------------------------------------------------------------------------
// elementwise conversions
// ---------------------------------------------------------------------------
__device__ __forceinline__ void split_store4(__half* h, __half* l, size_t idx, float4 v) {
    const __half h0 = __float2half_rn(v.x);
    const __half h1 = __float2half_rn(v.y);
    const __half h2 = __float2half_rn(v.z);
    const __half h3 = __float2half_rn(v.w);
    const __half l0 = __float2half_rn(v.x - __half2float(h0));
    const __half l1 = __float2half_rn(v.y - __half2float(h1));
    const __half l2 = __float2half_rn(v.z - __half2float(h2));
    const __half l3 = __float2half_rn(v.w - __half2float(h3));
    __half2* hp = (__half2*)(h + idx);
    __half2* lp = (__half2*)(l + idx);
    hp[0] = __halves2half2(h0, h1);  hp[1] = __halves2half2(h2, h3);
    lp[0] = __halves2half2(l0, l1);  lp[1] = __halves2half2(l2, l3);
}

// q, k, v -> plain fp16 (z = 0/1/2)
__global__ __launch_bounds__(256) void conv_in(
    const float* __restrict__ q, const float* __restrict__ k, const float* __restrict__ v,
    __half* __restrict__ q16, __half* __restrict__ k16, __half* __restrict__ v16, long n4)
{
    const int zz = blockIdx.z;
    const float* x = (zz == 0) ? q : (zz == 1) ? k : v;
    __half* h = (zz == 0) ? q16 : (zz == 1) ? k16 : v16;
    for (long i = blockIdx.x * 256 + threadIdx.x; i < n4; i += (long)gridDim.x * 256) {
        float4 vv = ((const float4*)x)[i];
        __half2* hp = (__half2*)(h + i * 4);
        hp[0] = __halves2half2(__float2half_rn(vv.x), __float2half_rn(vv.y));
        hp[1] = __halves2half2(__float2half_rn(vv.z), __float2half_rn(vv.w));
    }
}

// weights -> fp16 hi/lo (z = 0/1/2)
__global__ __launch_bounds__(256) void split_w(
    const float* __restrict__ Wq, const float* __restrict__ Wk, const float* __restrict__ Wv,
    __half* __restrict__ qh, __half* __restrict__ ql,
    __half* __restrict__ kh, __half* __restrict__ kl,
    __half* __restrict__ vh, __half* __restrict__ vl, long n4)
{
    const int zz = blockIdx.z;
    const float* x = (zz == 0) ? Wq : (zz == 1) ? Wk : Wv;
    __half* h = (zz == 0) ? qh : (zz == 1) ? kh : vh;
    __half* l = (zz == 0) ? ql : (zz == 1) ? kl : vl;
    for (long i = blockIdx.x * 256 + threadIdx.x; i < n4; i += (long)gridDim.x * 256) {
        float4 vv = ((const float4*)x)[i];
        split_store4(h, l, (size_t)i * 4, vv);
    }
}

// ---------------------------------------------------------------------------
// fused softmax (in place, fp32) + fp16 hi emission. One block per row.
// ---------------------------------------------------------------------------
__global__ __launch_bounds__(256) void softmax_fused(
    float* __restrict__ attn, __half* __restrict__ ah)
{
    const size_t row = blockIdx.x;
    float* p = attn + row * N_;
    const int t = threadIdx.x;
    __shared__ float red[8];

    float4 va = ((const float4*)p)[t];
    float4 vb = ((const float4*)p)[t + 256];

    float vmax = fmaxf(fmaxf(fmaxf(va.x, va.y), fmaxf(va.z, va.w)),
                       fmaxf(fmaxf(vb.x, vb.y), fmaxf(vb.z, vb.w)));
    #pragma unroll
    for (int o = 16; o > 0; o >>= 1) vmax = fmaxf(vmax, __shfl_xor_sync(0xFFFFFFFF, vmax, o));
    if ((t & 31) == 0) red[t >> 5] = vmax;
    __syncthreads();
    float m = fmaxf(fmaxf(fmaxf(red[0], red[1]), fmaxf(red[2], red[3])),
                    fmaxf(fmaxf(red[4], red[5]), fmaxf(red[6], red[7])));
    __syncthreads();

    va.x = __expf(va.x - m); va.y = __expf(va.y - m); va.z = __expf(va.z - m); va.w = __expf(va.w - m);
    vb.x = __expf(vb.x - m); vb.y = __expf(vb.y - m); vb.z = __expf(vb.z - m); vb.w = __expf(vb.w - m);

    float sum = va.x + va.y + va.z + va.w + vb.x + vb.y + vb.z + vb.w;
    #pragma unroll
    for (int o = 16; o > 0; o >>= 1) sum += __shfl_xor_sync(0xFFFFFFFF, sum, o);
    if ((t & 31) == 0) red[t >> 5] = sum;
    __syncthreads();
    const float inv = 1.0f / (red[0] + red[1] + red[2] + red[3] + red[4] + red[5] + red[6] + red[7]);

    va.x *= inv; va.y *= inv; va.z *= inv; va.w *= inv;
    vb.x *= inv; vb.y *= inv; vb.z *= inv; vb.w *= inv;

    ((float4*)p)[t]       = va;
    ((float4*)p)[t + 256] = vb;

    __half2* hp = (__half2*)(ah + row * N_ + (size_t)t * 4);
    hp[0] = __halves2half2(__float2half_rn(va.x), __float2half_rn(va.y));
    hp[1] = __halves2half2(__float2half_rn(va.z), __float2half_rn(va.w));
    __half2* hp2 = (__half2*)(ah + row * N_ + 1024 + (size_t)t * 4);
    hp2[0] = __halves2half2(__float2half_rn(vb.x), __float2half_rn(vb.y));
    hp2[1] = __halves2half2(__float2half_rn(vb.z), __float2half_rn(vb.w));
}

// ---------------------------------------------------------------------------
extern "C" void kernel_launch(void* const* d_in, const int* in_sizes, int n_in,
                              void* d_out, int out_size)
{
    const float* q  = (const float*)d_in[0];
    const float* k  = (const float*)d_in[1];
    const float* v  = (const float*)d_in[2];
    const float* Wq = (const float*)d_in[3];
    const float* Wk = (const float*)d_in[4];
    const float* Wv = (const float*)d_in[5];

    float* out  = (float*)d_out;                 // [B, N, E]
    float* attn = out + (long)B_ * N_ * E_;      // [B, N, N]

    cudaFuncSetAttribute(gemm2t, cudaFuncAttributeMaxDynamicSharedMemorySize, GEMM_SMEM_TOTAL);

    __half *q16, *k16, *v16;
    __half *Wqh, *Wql, *Wkh, *Wkl, *Wvh, *Wvl;
    __half *qph, *kph, *kpl, *vpth, *vptl, *ah;
    cudaGetSymbolAddress((void**)&q16, g_q16);
    cudaGetSymbolAddress((void**)&k16, g_k16);
    cudaGetSymbolAddress((void**)&v16, g_v16);
    cudaGetSymbolAddress((void**)&Wqh, g_Wqh); cudaGetSymbolAddress((void**)&Wql, g_Wql);
    cudaGetSymbolAddress((void**)&Wkh, g_Wkh); cudaGetSymbolAddress((void**)&Wkl, g_Wkl);
    cudaGetSymbolAddress((void**)&Wvh, g_Wvh); cudaGetSymbolAddress((void**)&Wvl, g_Wvl);
    cudaGetSymbolAddress((void**)&qph, g_qph);
    cudaGetSymbolAddress((void**)&kph, g_kph); cudaGetSymbolAddress((void**)&kpl, g_kpl);
    cudaGetSymbolAddress((void**)&vpth, g_vpth); cudaGetSymbolAddress((void**)&vptl, g_vptl);
    cudaGetSymbolAddress((void**)&ah, g_ah);

    const float c_eq  = rsqrtf((float)D_);
    const float scale = rsqrtf((float)E_);

    // 1-2) conversions (2 launches)
    {
        dim3 gi(2048, 1, 3);
        conv_in<<<gi, 256>>>(q, k, v, q16, k16, v16, QKV_ELEMS / 4);
        dim3 gw(256, 1, 3);
        split_w<<<gw, 256>>>(Wq, Wk, Wv, Wqh, Wql, Wkh, Wkl, Wvh, Wvl, W_ELEMS / 4);
    }

    // 3-5) projections: A = input fp16, B = W hi/lo
    {
        dim3 grid(E_ / 256, (B_ * N_) / 128, 1);
        gemm2t<<<grid, 256, GEMM_SMEM_TOTAL>>>(q16, Wqh, Wql, B_ * N_, E_, D_,
                                               0, 0, 0, c_eq, 4, qph, nullptr);
        gemm2t<<<grid, 256, GEMM_SMEM_TOTAL>>>(k16, Wkh, Wkl, B_ * N_, E_, D_,
                                               0, 0, 0, c_eq, 1, kph, kpl);
        gemm2t<<<grid, 256, GEMM_SMEM_TOTAL>>>(v16, Wvh, Wvl, B_ * N_, E_, D_,
                                               0, 0, 0, c_eq, 2, vpth, vptl);
    }

    // 6) dots = qp @ kp^T * scale -> attn region (fp32), batched
    {
        dim3 grid(N_ / 256, N_ / 128, B_);
        gemm2t<<<grid, 256, GEMM_SMEM_TOTAL>>>(qph, kph, kpl, N_, N_, E_,
                                               (long)N_ * E_, (long)N_ * E_, (long)N_ * N_,
                                               scale, 0, attn, nullptr);
    }

    // 7) softmax (in place) + fp16 hi emission
    softmax_fused<<<B_ * N_, 256>>>(attn, ah);

    // 8) out = attn @ vp (vp^T stored [b][e][n], K=N_=2048 contiguous)
    {
        dim3 grid(E_ / 256, N_ / 128, B_);
        gemm2t<<<grid, 256, GEMM_SMEM_TOTAL>>>(ah, vpth, vptl, N_, E_, N_,
                                               (long)N_ * N_, (long)E_ * N_, (long)N_ * E_,
                                               1.0f, 0, out, nullptr);
    }
}

// round 9
// speedup vs baseline: 2.4761x; 1.0008x over previous
#include <cuda_runtime.h>
#include <cuda_fp16.h>
#include <cstdint>
#include <math.h>

// Problem constants
#define B_ 8
#define N_ 2048
#define D_ 512
#define E_ 512

static constexpr long QKV_ELEMS  = (long)B_ * N_ * D_;   // 8,388,608
static constexpr long W_ELEMS    = (long)E_ * D_;        // 262,144
static constexpr long ATTN_ELEMS = (long)B_ * N_ * N_;   // 33,554,432

// ---------------- scratch (static device arrays; allocation-guard safe) ----
__device__ __half g_q16[QKV_ELEMS], g_k16[QKV_ELEMS], g_v16[QKV_ELEMS];
__device__ __half g_Wqh[W_ELEMS],   g_Wql[W_ELEMS];
__device__ __half g_Wkh[W_ELEMS],   g_Wkl[W_ELEMS];
__device__ __half g_Wvh[W_ELEMS],   g_Wvl[W_ELEMS];
__device__ __half g_qph[QKV_ELEMS];                       // q-proj: hi only
__device__ __half g_kph[QKV_ELEMS], g_kpl[QKV_ELEMS];
__device__ __half g_vpth[QKV_ELEMS], g_vptl[QKV_ELEMS];   // transposed [b][e][n]
__device__ __half g_ah[ATTN_ELEMS];                       // attn: hi only

// ---------------- PTX helpers ----------------------------------------------
__device__ __forceinline__ uint32_t smem_to_u32(const void* p) {
    uint32_t a;
    asm("{ .reg .u64 t; cvta.to.shared.u64 t, %1; cvt.u32.u64 %0, t; }" : "=r"(a) : "l"(p));
    return a;
}

#define CP_ASYNC16(smem_u32, gptr) \
    asm volatile("cp.async.cg.shared.global [%0], [%1], 16;" :: "r"(smem_u32), "l"(gptr) : "memory")
#define CP_ASYNC_COMMIT() asm volatile("cp.async.commit_group;" ::: "memory")
#define CP_ASYNC_WAIT1()  asm volatile("cp.async.wait_group 1;" ::: "memory")

__device__ __forceinline__ void ldsm_x4(uint32_t* r, uint32_t addr) {
    asm volatile("ldmatrix.sync.aligned.m8n8.x4.shared.b16 {%0,%1,%2,%3}, [%4];"
        : "=r"(r[0]), "=r"(r[1]), "=r"(r[2]), "=r"(r[3]) : "r"(addr));
}

__device__ __forceinline__ void mma16816(float* c, const uint32_t* a, const uint32_t* b) {
    asm volatile(
        "mma.sync.aligned.m16n8k16.row.col.f32.f16.f16.f32 "
        "{%0,%1,%2,%3}, {%4,%5,%6,%7}, {%8,%9}, {%0,%1,%2,%3};"
        : "+f"(c[0]), "+f"(c[1]), "+f"(c[2]), "+f"(c[3])
        : "r"(a[0]), "r"(a[1]), "r"(a[2]), "r"(a[3]), "r"(b[0]), "r"(b[1]));
}

// ---------------------------------------------------------------------------
// 2-product asymmetric-split GEMM:  C = alpha * A @ (Bh+Bl)^T
// A: [M,K] fp16 row-major K-contig; Bh/Bl: [N,K] fp16 hi/lo limbs.
// mode 0: C0 fp32 [M,N] (+ z*sC);  mode 1: C0/C1 fp16 hi/lo [M,N];
// mode 2: C0/C1 fp16 hi/lo transposed [b][E_][N_];  mode 4: C0 fp16 hi only.
// Block tile 128x256, BK=32, 8 warps (warp tile 64x64), 3-stage cp.async ring,
// B-fragment one-pair-ahead register prefetch, hi/lo MMA waves separated
// (dependent-MMA distance 8 to hide accumulator RAW latency).
// ---------------------------------------------------------------------------
#define BKH 32                              // K halves per slab
#define ROWH 40                             // padded row length in halves
#define ROWB 80                             // row bytes
#define A_TILE_B (128 * ROWB)               // 10240
#define B_TILE_B (256 * ROWB)               // 20480
#define STAGE_B (A_TILE_B + 2 * B_TILE_B)   // 51200: A, Bh, Bl
#define OFF_BH (A_TILE_B)
#define OFF_BL (A_TILE_B + B_TILE_B)
#define NSTAGE 3
#define GEMM_SMEM_TOTAL (NSTAGE * STAGE_B)  // 153600

__global__ __launch_bounds__(256, 1) void gemm2t(
    const __half* __restrict__ A,
    const __half* __restrict__ Bh, const __half* __restrict__ Bl,
    int M, int N, int K,
    long sA, long sB, long sC,
    float alpha, int mode,
    void* __restrict__ C0, void* __restrict__ C1)
{
    extern __shared__ char smem[];
    const uint32_t smem_base = smem_to_u32(smem);
    const int tid  = threadIdx.x;
    const int wid  = tid >> 5;
    const int lane = tid & 31;
    const int wm = wid & 1;        // 2 warps along M (64 rows each)
    const int wn = wid >> 1;       // 4 warps along N (64 cols each)
    const int z = blockIdx.z;

    A  += (long)z * sA;
    Bh += (long)z * sB;  Bl += (long)z * sB;

    const int m0 = blockIdx.y * 128;
    const int n0 = blockIdx.x * 256;

    float acc[4][8][4];
    #pragma unroll
    for (int i = 0; i < 4; i++)
        #pragma unroll
        for (int j = 0; j < 8; j++)
            #pragma unroll
            for (int c = 0; c < 4; c++) acc[i][j][c] = 0.0f;

    const int nslab = K / BKH;
    const int lrow = tid >> 2;
    const int lch  = tid & 3;

    // -------- async slab loader: 10 cp.async per thread --------
    auto load_slab = [&](int s) {
        const long koff = (long)s * BKH + lch * 8;
        const uint32_t st = smem_base + (uint32_t)(s % NSTAGE) * STAGE_B;
        const uint32_t so = (uint32_t)(lrow * ROWB + lch * 16);
        #pragma unroll
        for (int i = 0; i < 2; i++) {      // A: 128 rows
            const int r = lrow + 64 * i;
            const long g = (long)(m0 + r) * K + koff;
            CP_ASYNC16(st + so + i * (64 * ROWB), A + g);
        }
        #pragma unroll
        for (int i = 0; i < 4; i++) {      // B: 256 rows
            const int r = lrow + 64 * i;
            const long g = (long)(n0 + r) * K + koff;
            CP_ASYNC16(st + OFF_BH + so + i * (64 * ROWB), Bh + g);
            CP_ASYNC16(st + OFF_BL + so + i * (64 * ROWB), Bl + g);
        }
    };

    load_slab(0); CP_ASYNC_COMMIT();
    if (nslab > 1) load_slab(1);
    CP_ASYNC_COMMIT();

    const int am = lane & 15;
    const int ac = (lane >> 4) << 3;
    const int bn = ((lane >> 4) << 3) + (lane & 7);
    const int bc = ((lane >> 3) & 1) << 3;

    for (int s = 0; s < nslab; s++) {
        CP_ASYNC_WAIT1();          // slab s resident (only s+1 may be pending)
        __syncthreads();

        const uint32_t st = smem_base + (uint32_t)(s % NSTAGE) * STAGE_B;
        #pragma unroll
        for (int k16 = 0; k16 < 2; k16++) {
            // ---- A fragments: 4 ldsm.x4 ----
            uint32_t ra[4][4];
            #pragma unroll
            for (int mi = 0; mi < 4; mi++) {
                const uint32_t ao =
                    (uint32_t)((wm * 64 + mi * 16 + am) * ROWH + k16 * 16 + ac) * 2;
                ldsm_x4(ra[mi], st + ao);
            }
            // ---- B pair 0 prologue ----
            uint32_t th[2][4], tl[2][4];
            const uint32_t bbase =
                (uint32_t)((wn * 64 + bn) * ROWH + k16 * 16 + bc) * 2;
            ldsm_x4(th[0], st + OFF_BH + bbase);
            ldsm_x4(tl[0], st + OFF_BL + bbase);

            // issue next-next slab's loads behind the prologue ldsm latency
            if (k16 == 0) {
                if (s + 2 < nslab) load_slab(s + 2);
                CP_ASYNC_COMMIT();
            }

            // ---- pair loop: hi wave (8 indep MMAs) then lo wave (8) ----
            #pragma unroll
            for (int pair = 0; pair < 4; pair++) {
                const int cur = pair & 1;
                if (pair < 3) {
                    const uint32_t bo = bbase + (uint32_t)((pair + 1) * 16 * ROWH) * 2;
                    ldsm_x4(th[cur ^ 1], st + OFF_BH + bo);
                    ldsm_x4(tl[cur ^ 1], st + OFF_BL + bo);
                }
                // hi wave: 8 MMAs, all-distinct accumulators
                #pragma unroll
                for (int nj = 0; nj < 2; nj++) {
                    const uint32_t bh2[2] = { th[cur][nj * 2], th[cur][nj * 2 + 1] };
                    #pragma unroll
                    for (int mi = 0; mi < 4; mi++)
                        mma16816(acc[mi][pair * 2 + nj], ra[mi], bh2);
                }
                // lo wave: 8 MMAs, dependent on hi wave at distance 8
                #pragma unroll
                for (int nj = 0; nj < 2; nj++) {
                    const uint32_t bl2[2] = { tl[cur][nj * 2], tl[cur][nj * 2 + 1] };
                    #pragma unroll
                    for (int mi = 0; mi < 4; mi++)
                        mma16816(acc[mi][pair * 2 + nj], ra[mi], bl2);
                }
            }
        }
    }

    // -------- epilogue (register accumulators -> global) --------
    const int rq = lane >> 2;             // 0..7
    const int cq = (lane & 3) * 2;
    #pragma unroll
    for (int mi = 0; mi < 4; mi++) {
        #pragma unroll
        for (int ni = 0; ni < 8; ni++) {
            const int mA = m0 + wm * 64 + mi * 16 + rq;
            const int mB = mA + 8;
            const int n  = n0 + wn * 64 + ni * 8 + cq;
            const float v0 = acc[mi][ni][0] * alpha;
            const float v1 = acc[mi][ni][1] * alpha;
            const float v2 = acc[mi][ni][2] * alpha;
            const float v3 = acc[mi][ni][3] * alpha;
            if (mode == 0) {
                float* Cf = (float*)C0 + (size_t)z * sC;
                *(float2*)(Cf + (size_t)mA * N + n) = make_float2(v0, v1);
                *(float2*)(Cf + (size_t)mB * N + n) = make_float2(v2, v3);
            } else if (mode == 4) {
                *(__half2*)((__half*)C0 + (size_t)mA * N + n) =
                    __halves2half2(__float2half_rn(v0), __float2half_rn(v1));
                *(__half2*)((__half*)C0 + (size_t)mB * N + n) =
                    __halves2half2(__float2half_rn(v2), __float2half_rn(v3));
            } else if (mode == 1) {
                __half h0 = __float2half_rn(v0), h1 = __float2half_rn(v1);
                __half h2 = __float2half_rn(v2), h3 = __float2half_rn(v3);
                __half l0 = __float2half_rn(v0 - __half2float(h0));
                __half l1 = __float2half_rn(v1 - __half2float(h1));
                __half l2 = __float2half_rn(v2 - __half2float(h2));
                __half l3 = __float2half_rn(v3 - __half2float(h3));
                *(__half2*)((__half*)C0 + (size_t)mA * N + n) = __halves2half2(h0, h1);
                *(__half2*)((__half*)C0 + (size_t)mB * N + n) = __halves2half2(h2, h3);
                *(__half2*)((__half*)C1 + (size_t)mA * N + n) = __halves2half2(l0, l1);
                *(__half2*)((__half*)C1 + (size_t)mB * N + n) = __halves2half2(l2, l3);
            } else {
                // transposed store: C[b][e][n] with m -> (b, nn)
                const float vv[4] = { v0, v1, v2, v3 };
                #pragma unroll
                for (int e = 0; e < 4; e++) {
                    const int m = (e < 2) ? mA : mB;
                    const int nn2 = n + (e & 1);
                    const float val = vv[e];
                    const int bi = m >> 11;
                    const int mm = m & (N_ - 1);
                    const __half h = __float2half_rn(val);
                    const __half l = __float2half_rn(val - __half2float(h));
                    const size_t idx = ((size_t)bi * E_ + nn2) * N_ + mm;
                    ((__half*)C0)[idx] = h;
                    ((__half*)C1)[idx] = l;
                }
            }
        }
    }
}

// ---------------------------------------------------------------------------
// elementwise conversions
// ---------------------------------------------------------------------------
__device__ __forceinline__ void split_store4(__half* h, __half* l, size_t idx, float4 v) {
    const __half h0 = __float2half_rn(v.x);
    const __half h1 = __float2half_rn(v.y);
    const __half h2 = __float2half_rn(v.z);
    const __half h3 = __float2half_rn(v.w);
    const __half l0 = __float2half_rn(v.x - __half2float(h0));
    const __half l1 = __float2half_rn(v.y - __half2float(h1));
    const __half l2 = __float2half_rn(v.z - __half2float(h2));
    const __half l3 = __float2half_rn(v.w - __half2float(h3));
    __half2* hp = (__half2*)(h + idx);
    __half2* lp = (__half2*)(l + idx);
    hp[0] = __halves2half2(h0, h1);  hp[1] = __halves2half2(h2, h3);
    lp[0] = __halves2half2(l0, l1);  lp[1] = __halves2half2(l2, l3);
}

// q, k, v -> plain fp16 (z = 0/1/2)
__global__ __launch_bounds__(256) void conv_in(
    const float* __restrict__ q, const float* __restrict__ k, const float* __restrict__ v,
    __half* __restrict__ q16, __half* __restrict__ k16, __half* __restrict__ v16, long n4)
{
    const int zz = blockIdx.z;
    const float* x = (zz == 0) ? q : (zz == 1) ? k : v;
    __half* h = (zz == 0) ? q16 : (zz == 1) ? k16 : v16;
    for (long i = blockIdx.x * 256 + threadIdx.x; i < n4; i += (long)gridDim.x * 256) {
        float4 vv = ((const float4*)x)[i];
        __half2* hp = (__half2*)(h + i * 4);
        hp[0] = __halves2half2(__float2half_rn(vv.x), __float2half_rn(vv.y));
        hp[1] = __halves2half2(__float2half_rn(vv.z), __float2half_rn(vv.w));
    }
}

// weights -> fp16 hi/lo (z = 0/1/2)
__global__ __launch_bounds__(256) void split_w(
    const float* __restrict__ Wq, const float* __restrict__ Wk, const float* __restrict__ Wv,
    __half* __restrict__ qh, __half* __restrict__ ql,
    __half* __restrict__ kh, __half* __restrict__ kl,
    __half* __restrict__ vh, __half* __restrict__ vl, long n4)
{
    const int zz = blockIdx.z;
    const float* x = (zz == 0) ? Wq : (zz == 1) ? Wk : Wv;
    __half* h = (zz == 0) ? qh : (zz == 1) ? kh : vh;
    __half* l = (zz == 0) ? ql : (zz == 1) ? kl : vl;
    for (long i = blockIdx.x * 256 + threadIdx.x; i < n4; i += (long)gridDim.x * 256) {
        float4 vv = ((const float4*)x)[i];
        split_store4(h, l, (size_t)i * 4, vv);
    }
}

// ---------------------------------------------------------------------------
// fused softmax (in place, fp32) + fp16 hi emission. One block per row.
// ---------------------------------------------------------------------------
__global__ __launch_bounds__(256) void softmax_fused(
    float* __restrict__ attn, __half* __restrict__ ah)
{
    const size_t row = blockIdx.x;
    float* p = attn + row * N_;
    const int t = threadIdx.x;
    __shared__ float red[8];

    float4 va = ((const float4*)p)[t];
    float4 vb = ((const float4*)p)[t + 256];

    float vmax = fmaxf(fmaxf(fmaxf(va.x, va.y), fmaxf(va.z, va.w)),
                       fmaxf(fmaxf(vb.x, vb.y), fmaxf(vb.z, vb.w)));
    #pragma unroll
    for (int o = 16; o > 0; o >>= 1) vmax = fmaxf(vmax, __shfl_xor_sync(0xFFFFFFFF, vmax, o));
    if ((t & 31) == 0) red[t >> 5] = vmax;
    __syncthreads();
    float m = fmaxf(fmaxf(fmaxf(red[0], red[1]), fmaxf(red[2], red[3])),
                    fmaxf(fmaxf(red[4], red[5]), fmaxf(red[6], red[7])));
    __syncthreads();

    va.x = __expf(va.x - m); va.y = __expf(va.y - m); va.z = __expf(va.z - m); va.w = __expf(va.w - m);
    vb.x = __expf(vb.x - m); vb.y = __expf(vb.y - m); vb.z = __expf(vb.z - m); vb.w = __expf(vb.w - m);

    float sum = va.x + va.y + va.z + va.w + vb.x + vb.y + vb.z + vb.w;
    #pragma unroll
    for (int o = 16; o > 0; o >>= 1) sum += __shfl_xor_sync(0xFFFFFFFF, sum, o);
    if ((t & 31) == 0) red[t >> 5] = sum;
    __syncthreads();
    const float inv = 1.0f / (red[0] + red[1] + red[2] + red[3] + red[4] + red[5] + red[6] + red[7]);

    va.x *= inv; va.y *= inv; va.z *= inv; va.w *= inv;
    vb.x *= inv; vb.y *= inv; vb.z *= inv; vb.w *= inv;

    ((float4*)p)[t]       = va;
    ((float4*)p)[t + 256] = vb;

    __half2* hp = (__half2*)(ah + row * N_ + (size_t)t * 4);
    hp[0] = __halves2half2(__float2half_rn(va.x), __float2half_rn(va.y));
    hp[1] = __halves2half2(__float2half_rn(va.z), __float2half_rn(va.w));
    __half2* hp2 = (__half2*)(ah + row * N_ + 1024 + (size_t)t * 4);
    hp2[0] = __halves2half2(__float2half_rn(vb.x), __float2half_rn(vb.y));
    hp2[1] = __halves2half2(__float2half_rn(vb.z), __float2half_rn(vb.w));
}

// ---------------------------------------------------------------------------
extern "C" void kernel_launch(void* const* d_in, const int* in_sizes, int n_in,
                              void* d_out, int out_size)
{
    const float* q  = (const float*)d_in[0];
    const float* k  = (const float*)d_in[1];
    const float* v  = (const float*)d_in[2];
    const float* Wq = (const float*)d_in[3];
    const float* Wk = (const float*)d_in[4];
    const float* Wv = (const float*)d_in[5];

    float* out  = (float*)d_out;                 // [B, N, E]
    float* attn = out + (long)B_ * N_ * E_;      // [B, N, N]

    cudaFuncSetAttribute(gemm2t, cudaFuncAttributeMaxDynamicSharedMemorySize, GEMM_SMEM_TOTAL);

    __half *q16, *k16, *v16;
    __half *Wqh, *Wql, *Wkh, *Wkl, *Wvh, *Wvl;
    __half *qph, *kph, *kpl, *vpth, *vptl, *ah;
    cudaGetSymbolAddress((void**)&q16, g_q16);
    cudaGetSymbolAddress((void**)&k16, g_k16);
    cudaGetSymbolAddress((void**)&v16, g_v16);
    cudaGetSymbolAddress((void**)&Wqh, g_Wqh); cudaGetSymbolAddress((void**)&Wql, g_Wql);
    cudaGetSymbolAddress((void**)&Wkh, g_Wkh); cudaGetSymbolAddress((void**)&Wkl, g_Wkl);
    cudaGetSymbolAddress((void**)&Wvh, g_Wvh); cudaGetSymbolAddress((void**)&Wvl, g_Wvl);
    cudaGetSymbolAddress((void**)&qph, g_qph);
    cudaGetSymbolAddress((void**)&kph, g_kph); cudaGetSymbolAddress((void**)&kpl, g_kpl);
    cudaGetSymbolAddress((void**)&vpth, g_vpth); cudaGetSymbolAddress((void**)&vptl, g_vptl);
    cudaGetSymbolAddress((void**)&ah, g_ah);

    const float c_eq  = rsqrtf((float)D_);
    const float scale = rsqrtf((float)E_);

    // 1-2) conversions (2 launches)
    {
        dim3 gi(2048, 1, 3);
        conv_in<<<gi, 256>>>(q, k, v, q16, k16, v16, QKV_ELEMS / 4);
        dim3 gw(256, 1, 3);
        split_w<<<gw, 256>>>(Wq, Wk, Wv, Wqh, Wql, Wkh, Wkl, Wvh, Wvl, W_ELEMS / 4);
    }

    // 3-5) projections: A = input fp16, B = W hi/lo
    {
        dim3 grid(E_ / 256, (B_ * N_) / 128, 1);
        gemm2t<<<grid, 256, GEMM_SMEM_TOTAL>>>(q16, Wqh, Wql, B_ * N_, E_, D_,
                                               0, 0, 0, c_eq, 4, qph, nullptr);
        gemm2t<<<grid, 256, GEMM_SMEM_TOTAL>>>(k16, Wkh, Wkl, B_ * N_, E_, D_,
                                               0, 0, 0, c_eq, 1, kph, kpl);
        gemm2t<<<grid, 256, GEMM_SMEM_TOTAL>>>(v16, Wvh, Wvl, B_ * N_, E_, D_,
                                               0, 0, 0, c_eq, 2, vpth, vptl);
    }

    // 6) dots = qp @ kp^T * scale -> attn region (fp32), batched
    {
        dim3 grid(N_ / 256, N_ / 128, B_);
        gemm2t<<<grid, 256, GEMM_SMEM_TOTAL>>>(qph, kph, kpl, N_, N_, E_,
                                               (long)N_ * E_, (long)N_ * E_, (long)N_ * N_,
                                               scale, 0, attn, nullptr);
    }

    // 7) softmax (in place) + fp16 hi emission
    softmax_fused<<<B_ * N_, 256>>>(attn, ah);

    // 8) out = attn @ vp (vp^T stored [b][e][n], K=N_=2048 contiguous)
    {
        dim3 grid(E_ / 256, N_ / 128, B_);
        gemm2t<<<grid, 256, GEMM_SMEM_TOTAL>>>(ah, vpth, vptl, N_, E_, N_,
                                               (long)N_ * N_, (long)E_ * N_, (long)N_ * E_,
                                               1.0f, 0, out, nullptr);
    }
}

// round 10
// speedup vs baseline: 2.5752x; 1.0400x over previous
#include <cuda_runtime.h>
#include <cuda_fp16.h>
#include <cstdint>
#include <math.h>

// Problem constants
#define B_ 8
#define N_ 2048
#define D_ 512
#define E_ 512

static constexpr long QKV_ELEMS  = (long)B_ * N_ * D_;   // 8,388,608
static constexpr long W_ELEMS    = (long)E_ * D_;        // 262,144
static constexpr long ATTN_ELEMS = (long)B_ * N_ * N_;   // 33,554,432

// ---------------- scratch (static device arrays; allocation-guard safe) ----
__device__ __half g_q16[QKV_ELEMS], g_k16[QKV_ELEMS], g_v16[QKV_ELEMS];
__device__ __half g_Wqh[W_ELEMS],   g_Wql[W_ELEMS];
__device__ __half g_Wkh[W_ELEMS],   g_Wkl[W_ELEMS];
__device__ __half g_Wvh[W_ELEMS],   g_Wvl[W_ELEMS];
__device__ __half g_qph[QKV_ELEMS];                       // q-proj: hi only
__device__ __half g_kph[QKV_ELEMS], g_kpl[QKV_ELEMS];
__device__ __half g_vpth[QKV_ELEMS], g_vptl[QKV_ELEMS];   // transposed [b][e][n]
__device__ __half g_ah[ATTN_ELEMS];                       // attn: hi only

// ---------------- PTX helpers ----------------------------------------------
__device__ __forceinline__ uint32_t smem_to_u32(const void* p) {
    uint32_t a;
    asm("{ .reg .u64 t; cvta.to.shared.u64 t, %1; cvt.u32.u64 %0, t; }" : "=r"(a) : "l"(p));
    return a;
}

#define CP_ASYNC16(smem_u32, gptr) \
    asm volatile("cp.async.cg.shared.global [%0], [%1], 16;" :: "r"(smem_u32), "l"(gptr) : "memory")
#define CP_ASYNC_COMMIT() asm volatile("cp.async.commit_group;" ::: "memory")
#define CP_ASYNC_WAIT1()  asm volatile("cp.async.wait_group 1;" ::: "memory")

__device__ __forceinline__ void ldsm_x4(uint32_t* r, uint32_t addr) {
    asm volatile("ldmatrix.sync.aligned.m8n8.x4.shared.b16 {%0,%1,%2,%3}, [%4];"
        : "=r"(r[0]), "=r"(r[1]), "=r"(r[2]), "=r"(r[3]) : "r"(addr));
}

__device__ __forceinline__ void mma16816(float* c, const uint32_t* a, const uint32_t* b) {
    asm volatile(
        "mma.sync.aligned.m16n8k16.row.col.f32.f16.f16.f32 "
        "{%0,%1,%2,%3}, {%4,%5,%6,%7}, {%8,%9}, {%0,%1,%2,%3};"
        : "+f"(c[0]), "+f"(c[1]), "+f"(c[2]), "+f"(c[3])
        : "r"(a[0]), "r"(a[1]), "r"(a[2]), "r"(a[3]), "r"(b[0]), "r"(b[1]));
}

// ---------------------------------------------------------------------------
// 2-product asymmetric-split GEMM:  C = alpha * A @ (Bh+Bl)^T
// A: [M,K] fp16 row-major K-contig; Bh/Bl: [N,K] fp16 hi/lo limbs.
// mode 0: C0 fp32 [M,N] (+ z*sC);  mode 1: C0/C1 fp16 hi/lo [M,N];
// mode 2: C0/C1 fp16 hi/lo transposed [b][E_][N_];  mode 4: C0 fp16 hi only.
// Block tile 128x128, BK=32, 8 warps (warp tile 64x32), 3-stage cp.async ring,
// 2 CTAs/SM (regs capped at 128) so slab-boundary stalls overlap across CTAs.
// ---------------------------------------------------------------------------
#define BKH 32                              // K halves per slab
#define ROWH 40                             // padded row length in halves
#define ROWB 80                             // row bytes
#define T_TILE_B (128 * ROWB)               // 10240
#define STAGE_B (3 * T_TILE_B)              // 30720: A, Bh, Bl
#define OFF_BH (T_TILE_B)
#define OFF_BL (2 * T_TILE_B)
#define NSTAGE 3
#define GEMM_SMEM_TOTAL (NSTAGE * STAGE_B)  // 92160 -> 2 CTAs/SM

__global__ __launch_bounds__(256, 2) void gemm2t(
    const __half* __restrict__ A,
    const __half* __restrict__ Bh, const __half* __restrict__ Bl,
    int M, int N, int K,
    long sA, long sB, long sC,
    float alpha, int mode,
    void* __restrict__ C0, void* __restrict__ C1)
{
    extern __shared__ char smem[];
    const uint32_t smem_base = smem_to_u32(smem);
    const int tid  = threadIdx.x;
    const int wid  = tid >> 5;
    const int lane = tid & 31;
    const int wm = wid & 1;        // 2 warps along M (64 rows each)
    const int wn = wid >> 1;       // 4 warps along N (32 cols each)
    const int z = blockIdx.z;

    A  += (long)z * sA;
    Bh += (long)z * sB;  Bl += (long)z * sB;

    const int m0 = blockIdx.y * 128;
    const int n0 = blockIdx.x * 128;

    float acc[4][4][4];
    #pragma unroll
    for (int i = 0; i < 4; i++)
        #pragma unroll
        for (int j = 0; j < 4; j++)
            #pragma unroll
            for (int c = 0; c < 4; c++) acc[i][j][c] = 0.0f;

    const int nslab = K / BKH;
    const int lrow = tid >> 2;        // 0..63
    const int lch  = tid & 3;

    // -------- async slab loader: 6 cp.async per thread --------
    auto load_slab = [&](int s) {
        const long koff = (long)s * BKH + lch * 8;
        const uint32_t st = smem_base + (uint32_t)(s % NSTAGE) * STAGE_B;
        const uint32_t so = (uint32_t)(lrow * ROWB + lch * 16);
        #pragma unroll
        for (int i = 0; i < 2; i++) {
            const int r = lrow + 64 * i;
            const long ga = (long)(m0 + r) * K + koff;
            const long gb = (long)(n0 + r) * K + koff;
            const uint32_t ro = so + (uint32_t)i * (64 * ROWB);
            CP_ASYNC16(st +          ro, A  + ga);
            CP_ASYNC16(st + OFF_BH + ro, Bh + gb);
            CP_ASYNC16(st + OFF_BL + ro, Bl + gb);
        }
    };

    load_slab(0); CP_ASYNC_COMMIT();
    if (nslab > 1) load_slab(1);
    CP_ASYNC_COMMIT();

    const int am = lane & 15;
    const int ac = (lane >> 4) << 3;
    const int bn = ((lane >> 4) << 3) + (lane & 7);
    const int bc = ((lane >> 3) & 1) << 3;

    for (int s = 0; s < nslab; s++) {
        CP_ASYNC_WAIT1();          // slab s resident (only s+1 may be pending)
        __syncthreads();

        const uint32_t st = smem_base + (uint32_t)(s % NSTAGE) * STAGE_B;
        #pragma unroll
        for (int k16 = 0; k16 < 2; k16++) {
            // ---- A fragments: 4 ldsm.x4 ----
            uint32_t ra[4][4];
            #pragma unroll
            for (int mi = 0; mi < 4; mi++) {
                const uint32_t ao =
                    (uint32_t)((wm * 64 + mi * 16 + am) * ROWH + k16 * 16 + ac) * 2;
                ldsm_x4(ra[mi], st + ao);
            }
            // ---- B pair 0 prologue ----
            uint32_t th[2][4], tl[2][4];
            const uint32_t bbase =
                (uint32_t)((wn * 32 + bn) * ROWH + k16 * 16 + bc) * 2;
            ldsm_x4(th[0], st + OFF_BH + bbase);
            ldsm_x4(tl[0], st + OFF_BL + bbase);

            // issue next-next slab's loads behind the prologue ldsm latency
            if (k16 == 0) {
                if (s + 2 < nslab) load_slab(s + 2);
                CP_ASYNC_COMMIT();
            }

            // ---- pair loop (2 pairs of 16 cols) with one-ahead B prefetch ----
            #pragma unroll
            for (int pair = 0; pair < 2; pair++) {
                const int cur = pair & 1;
                if (pair < 1) {
                    const uint32_t bo = bbase + (uint32_t)(16 * ROWH) * 2;
                    ldsm_x4(th[cur ^ 1], st + OFF_BH + bo);
                    ldsm_x4(tl[cur ^ 1], st + OFF_BL + bo);
                }
                #pragma unroll
                for (int nj = 0; nj < 2; nj++) {
                    const uint32_t bh2[2] = { th[cur][nj * 2], th[cur][nj * 2 + 1] };
                    #pragma unroll
                    for (int mi = 0; mi < 4; mi++)
                        mma16816(acc[mi][pair * 2 + nj], ra[mi], bh2);
                }
                #pragma unroll
                for (int nj = 0; nj < 2; nj++) {
                    const uint32_t bl2[2] = { tl[cur][nj * 2], tl[cur][nj * 2 + 1] };
                    #pragma unroll
                    for (int mi = 0; mi < 4; mi++)
                        mma16816(acc[mi][pair * 2 + nj], ra[mi], bl2);
                }
            }
        }
    }

    // -------- epilogue (register accumulators -> global) --------
    const int rq = lane >> 2;             // 0..7
    const int cq = (lane & 3) * 2;
    #pragma unroll
    for (int mi = 0; mi < 4; mi++) {
        #pragma unroll
        for (int ni = 0; ni < 4; ni++) {
            const int mA = m0 + wm * 64 + mi * 16 + rq;
            const int mB = mA + 8;
            const int n  = n0 + wn * 32 + ni * 8 + cq;
            const float v0 = acc[mi][ni][0] * alpha;
            const float v1 = acc[mi][ni][1] * alpha;
            const float v2 = acc[mi][ni][2] * alpha;
            const float v3 = acc[mi][ni][3] * alpha;
            if (mode == 0) {
                float* Cf = (float*)C0 + (size_t)z * sC;
                *(float2*)(Cf + (size_t)mA * N + n) = make_float2(v0, v1);
                *(float2*)(Cf + (size_t)mB * N + n) = make_float2(v2, v3);
            } else if (mode == 4) {
                *(__half2*)((__half*)C0 + (size_t)mA * N + n) =
                    __halves2half2(__float2half_rn(v0), __float2half_rn(v1));
                *(__half2*)((__half*)C0 + (size_t)mB * N + n) =
                    __halves2half2(__float2half_rn(v2), __float2half_rn(v3));
            } else if (mode == 1) {
                __half h0 = __float2half_rn(v0), h1 = __float2half_rn(v1);
                __half h2 = __float2half_rn(v2), h3 = __float2half_rn(v3);
                __half l0 = __float2half_rn(v0 - __half2float(h0));
                __half l1 = __float2half_rn(v1 - __half2float(h1));
                __half l2 = __float2half_rn(v2 - __half2float(h2));
                __half l3 = __float2half_rn(v3 - __half2float(h3));
                *(__half2*)((__half*)C0 + (size_t)mA * N + n) = __halves2half2(h0, h1);
                *(__half2*)((__half*)C0 + (size_t)mB * N + n) = __halves2half2(h2, h3);
                *(__half2*)((__half*)C1 + (size_t)mA * N + n) = __halves2half2(l0, l1);
                *(__half2*)((__half*)C1 + (size_t)mB * N + n) = __halves2half2(l2, l3);
            } else {
                // transposed store: C[b][e][n] with m -> (b, nn)
                const float vv[4] = { v0, v1, v2, v3 };
                #pragma unroll
                for (int e = 0; e < 4; e++) {
                    const int m = (e < 2) ? mA : mB;
                    const int nn2 = n + (e & 1);
                    const float val = vv[e];
                    const int bi = m >> 11;
                    const int mm = m & (N_ - 1);
                    const __half h = __float2half_rn(val);
                    const __half l = __float2half_rn(val - __half2float(h));
                    const size_t idx = ((size_t)bi * E_ + nn2) * N_ + mm;
                    ((__half*)C0)[idx] = h;
                    ((__half*)C1)[idx] = l;
                }
            }
        }
    }
}

// ---------------------------------------------------------------------------
// elementwise conversions
// ---------------------------------------------------------------------------
__device__ __forceinline__ void split_store4(__half* h, __half* l, size_t idx, float4 v) {
    const __half h0 = __float2half_rn(v.x);
    const __half h1 = __float2half_rn(v.y);
    const __half h2 = __float2half_rn(v.z);
    const __half h3 = __float2half_rn(v.w);
    const __half l0 = __float2half_rn(v.x - __half2float(h0));
    const __half l1 = __float2half_rn(v.y - __half2float(h1));
    const __half l2 = __float2half_rn(v.z - __half2float(h2));
    const __half l3 = __float2half_rn(v.w - __half2float(h3));
    __half2* hp = (__half2*)(h + idx);
    __half2* lp = (__half2*)(l + idx);
    hp[0] = __halves2half2(h0, h1);  hp[1] = __halves2half2(h2, h3);
    lp[0] = __halves2half2(l0, l1);  lp[1] = __halves2half2(l2, l3);
}

// q, k, v -> plain fp16 (z = 0/1/2)
__global__ __launch_bounds__(256) void conv_in(
    const float* __restrict__ q, const float* __restrict__ k, const float* __restrict__ v,
    __half* __restrict__ q16, __half* __restrict__ k16, __half* __restrict__ v16, long n4)
{
    const int zz = blockIdx.z;
    const float* x = (zz == 0) ? q : (zz == 1) ? k : v;
    __half* h = (zz == 0) ? q16 : (zz == 1) ? k16 : v16;
    for (long i = blockIdx.x * 256 + threadIdx.x; i < n4; i += (long)gridDim.x * 256) {
        float4 vv = ((const float4*)x)[i];
        __half2* hp = (__half2*)(h + i * 4);
        hp[0] = __halves2half2(__float2half_rn(vv.x), __float2half_rn(vv.y));
        hp[1] = __halves2half2(__float2half_rn(vv.z), __float2half_rn(vv.w));
    }
}

// weights -> fp16 hi/lo (z = 0/1/2)
__global__ __launch_bounds__(256) void split_w(
    const float* __restrict__ Wq, const float* __restrict__ Wk, const float* __restrict__ Wv,
    __half* __restrict__ qh, __half* __restrict__ ql,
    __half* __restrict__ kh, __half* __restrict__ kl,
    __half* __restrict__ vh, __half* __restrict__ vl, long n4)
{
    const int zz = blockIdx.z;
    const float* x = (zz == 0) ? Wq : (zz == 1) ? Wk : Wv;
    __half* h = (zz == 0) ? qh : (zz == 1) ? kh : vh;
    __half* l = (zz == 0) ? ql : (zz == 1) ? kl : vl;
    for (long i = blockIdx.x * 256 + threadIdx.x; i < n4; i += (long)gridDim.x * 256) {
        float4 vv = ((const float4*)x)[i];
        split_store4(h, l, (size_t)i * 4, vv);
    }
}

// ---------------------------------------------------------------------------
// fused softmax (in place, fp32) + fp16 hi emission. One block per row.
// ---------------------------------------------------------------------------
__global__ __launch_bounds__(256) void softmax_fused(
    float* __restrict__ attn, __half* __restrict__ ah)
{
    const size_t row = blockIdx.x;
    float* p = attn + row * N_;
    const int t = threadIdx.x;
    __shared__ float red[8];

    float4 va = ((const float4*)p)[t];
    float4 vb = ((const float4*)p)[t + 256];

    float vmax = fmaxf(fmaxf(fmaxf(va.x, va.y), fmaxf(va.z, va.w)),
                       fmaxf(fmaxf(vb.x, vb.y), fmaxf(vb.z, vb.w)));
    #pragma unroll
    for (int o = 16; o > 0; o >>= 1) vmax = fmaxf(vmax, __shfl_xor_sync(0xFFFFFFFF, vmax, o));
    if ((t & 31) == 0) red[t >> 5] = vmax;
    __syncthreads();
    float m = fmaxf(fmaxf(fmaxf(red[0], red[1]), fmaxf(red[2], red[3])),
                    fmaxf(fmaxf(red[4], red[5]), fmaxf(red[6], red[7])));
    __syncthreads();

    va.x = __expf(va.x - m); va.y = __expf(va.y - m); va.z = __expf(va.z - m); va.w = __expf(va.w - m);
    vb.x = __expf(vb.x - m); vb.y = __expf(vb.y - m); vb.z = __expf(vb.z - m); vb.w = __expf(vb.w - m);

    float sum = va.x + va.y + va.z + va.w + vb.x + vb.y + vb.z + vb.w;
    #pragma unroll
    for (int o = 16; o > 0; o >>= 1) sum += __shfl_xor_sync(0xFFFFFFFF, sum, o);
    if ((t & 31) == 0) red[t >> 5] = sum;
    __syncthreads();
    const float inv = 1.0f / (red[0] + red[1] + red[2] + red[3] + red[4] + red[5] + red[6] + red[7]);

    va.x *= inv; va.y *= inv; va.z *= inv; va.w *= inv;
    vb.x *= inv; vb.y *= inv; vb.z *= inv; vb.w *= inv;

    ((float4*)p)[t]       = va;
    ((float4*)p)[t + 256] = vb;

    __half2* hp = (__half2*)(ah + row * N_ + (size_t)t * 4);
    hp[0] = __halves2half2(__float2half_rn(va.x), __float2half_rn(va.y));
    hp[1] = __halves2half2(__float2half_rn(va.z), __float2half_rn(va.w));
    __half2* hp2 = (__half2*)(ah + row * N_ + 1024 + (size_t)t * 4);
    hp2[0] = __halves2half2(__float2half_rn(vb.x), __float2half_rn(vb.y));
    hp2[1] = __halves2half2(__float2half_rn(vb.z), __float2half_rn(vb.w));
}

// ---------------------------------------------------------------------------
extern "C" void kernel_launch(void* const* d_in, const int* in_sizes, int n_in,
                              void* d_out, int out_size)
{
    const float* q  = (const float*)d_in[0];
    const float* k  = (const float*)d_in[1];
    const float* v  = (const float*)d_in[2];
    const float* Wq = (const float*)d_in[3];
    const float* Wk = (const float*)d_in[4];
    const float* Wv = (const float*)d_in[5];

    float* out  = (float*)d_out;                 // [B, N, E]
    float* attn = out + (long)B_ * N_ * E_;      // [B, N, N]

    cudaFuncSetAttribute(gemm2t, cudaFuncAttributeMaxDynamicSharedMemorySize, GEMM_SMEM_TOTAL);

    __half *q16, *k16, *v16;
    __half *Wqh, *Wql, *Wkh, *Wkl, *Wvh, *Wvl;
    __half *qph, *kph, *kpl, *vpth, *vptl, *ah;
    cudaGetSymbolAddress((void**)&q16, g_q16);
    cudaGetSymbolAddress((void**)&k16, g_k16);
    cudaGetSymbolAddress((void**)&v16, g_v16);
    cudaGetSymbolAddress((void**)&Wqh, g_Wqh); cudaGetSymbolAddress((void**)&Wql, g_Wql);
    cudaGetSymbolAddress((void**)&Wkh, g_Wkh); cudaGetSymbolAddress((void**)&Wkl, g_Wkl);
    cudaGetSymbolAddress((void**)&Wvh, g_Wvh); cudaGetSymbolAddress((void**)&Wvl, g_Wvl);
    cudaGetSymbolAddress((void**)&qph, g_qph);
    cudaGetSymbolAddress((void**)&kph, g_kph); cudaGetSymbolAddress((void**)&kpl, g_kpl);
    cudaGetSymbolAddress((void**)&vpth, g_vpth); cudaGetSymbolAddress((void**)&vptl, g_vptl);
    cudaGetSymbolAddress((void**)&ah, g_ah);

    const float c_eq  = rsqrtf((float)D_);
    const float scale = rsqrtf((float)E_);

    // 1-2) conversions (2 launches)
    {
        dim3 gi(2048, 1, 3);
        conv_in<<<gi, 256>>>(q, k, v, q16, k16, v16, QKV_ELEMS / 4);
        dim3 gw(256, 1, 3);
        split_w<<<gw, 256>>>(Wq, Wk, Wv, Wqh, Wql, Wkh, Wkl, Wvh, Wvl, W_ELEMS / 4);
    }

    // 3-5) projections: A = input fp16, B = W hi/lo
    {
        dim3 grid(E_ / 128, (B_ * N_) / 128, 1);
        gemm2t<<<grid, 256, GEMM_SMEM_TOTAL>>>(q16, Wqh, Wql, B_ * N_, E_, D_,
                                               0, 0, 0, c_eq, 4, qph, nullptr);
        gemm2t<<<grid, 256, GEMM_SMEM_TOTAL>>>(k16, Wkh, Wkl, B_ * N_, E_, D_,
                                               0, 0, 0, c_eq, 1, kph, kpl);
        gemm2t<<<grid, 256, GEMM_SMEM_TOTAL>>>(v16, Wvh, Wvl, B_ * N_, E_, D_,
                                               0, 0, 0, c_eq, 2, vpth, vptl);
    }

    // 6) dots = qp @ kp^T * scale -> attn region (fp32), batched
    {
        dim3 grid(N_ / 128, N_ / 128, B_);
        gemm2t<<<grid, 256, GEMM_SMEM_TOTAL>>>(qph, kph, kpl, N_, N_, E_,
                                               (long)N_ * E_, (long)N_ * E_, (long)N_ * N_,
                                               scale, 0, attn, nullptr);
    }

    // 7) softmax (in place) + fp16 hi emission
    softmax_fused<<<B_ * N_, 256>>>(attn, ah);

    // 8) out = attn @ vp (vp^T stored [b][e][n], K=N_=2048 contiguous)
    {
        dim3 grid(E_ / 128, N_ / 128, B_);
        gemm2t<<<grid, 256, GEMM_SMEM_TOTAL>>>(ah, vpth, vptl, N_, E_, N_,
                                               (long)N_ * N_, (long)E_ * N_, (long)N_ * E_,
                                               1.0f, 0, out, nullptr);
    }
}

// round 11
// speedup vs baseline: 3.3632x; 1.3060x over previous
#include <cuda_runtime.h>
#include <cuda_fp16.h>
#include <cstdint>
#include <math.h>

// Problem constants
#define B_ 8
#define N_ 2048
#define D_ 512
#define E_ 512

static constexpr long QKV_ELEMS  = (long)B_ * N_ * D_;   // 8,388,608
static constexpr long W_ELEMS    = (long)E_ * D_;        // 262,144
static constexpr long ATTN_ELEMS = (long)B_ * N_ * N_;   // 33,554,432

// ---------------- scratch (static device arrays; allocation-guard safe) ----
__device__ __half g_q16[QKV_ELEMS], g_k16[QKV_ELEMS], g_v16[QKV_ELEMS];
__device__ __half g_Wqh[W_ELEMS],   g_Wql[W_ELEMS];
__device__ __half g_Wkh[W_ELEMS],   g_Wkl[W_ELEMS];
__device__ __half g_Wvh[W_ELEMS],   g_Wvl[W_ELEMS];
__device__ __half g_qph[QKV_ELEMS];                       // q-proj: hi only
__device__ __half g_kph[QKV_ELEMS];                       // k-proj: hi only
__device__ __half g_vpth[QKV_ELEMS];                      // v-proj: hi only, [b][e][n]
__device__ __half g_ah[ATTN_ELEMS];                       // attn: hi only

// ---------------- PTX helpers ----------------------------------------------
__device__ __forceinline__ uint32_t smem_to_u32(const void* p) {
    uint32_t a;
    asm("{ .reg .u64 t; cvta.to.shared.u64 t, %1; cvt.u32.u64 %0, t; }" : "=r"(a) : "l"(p));
    return a;
}

#define CP_ASYNC16(smem_u32, gptr) \
    asm volatile("cp.async.cg.shared.global [%0], [%1], 16;" :: "r"(smem_u32), "l"(gptr) : "memory")
#define CP_ASYNC_COMMIT() asm volatile("cp.async.commit_group;" ::: "memory")
#define CP_ASYNC_WAIT1()  asm volatile("cp.async.wait_group 1;" ::: "memory")

__device__ __forceinline__ void ldsm_x4(uint32_t* r, uint32_t addr) {
    asm volatile("ldmatrix.sync.aligned.m8n8.x4.shared.b16 {%0,%1,%2,%3}, [%4];"
        : "=r"(r[0]), "=r"(r[1]), "=r"(r[2]), "=r"(r[3]) : "r"(addr));
}

__device__ __forceinline__ void mma16816(float* c, const uint32_t* a, const uint32_t* b) {
    asm volatile(
        "mma.sync.aligned.m16n8k16.row.col.f32.f16.f16.f32 "
        "{%0,%1,%2,%3}, {%4,%5,%6,%7}, {%8,%9}, {%0,%1,%2,%3};"
        : "+f"(c[0]), "+f"(c[1]), "+f"(c[2]), "+f"(c[3])
        : "r"(a[0]), "r"(a[1]), "r"(a[2]), "r"(a[3]), "r"(b[0]), "r"(b[1]));
}

// ---------------------------------------------------------------------------
// GEMM:  C = alpha * A @ (Bh [+ Bl])^T   (nprod = 1 or 2 fp16 B-limbs)
// A: [M,K] fp16 row-major K-contig; Bh/Bl: [N,K] fp16.
// mode 0: C0 fp32 [M,N] (+ z*sC);  mode 4: C0 fp16 [M,N];
// mode 2: C0 fp16 transposed [b][E_][N_].
// Block tile 128x128, BK=32, 8 warps (warp tile 64x32), 3-stage cp.async ring,
// 2 CTAs/SM.
// ---------------------------------------------------------------------------
#define BKH 32                              // K halves per slab
#define ROWH 40                             // padded row length in halves
#define ROWB 80                             // row bytes
#define T_TILE_B (128 * ROWB)               // 10240
#define STAGE_B (3 * T_TILE_B)              // 30720: A, Bh, Bl
#define OFF_BH (T_TILE_B)
#define OFF_BL (2 * T_TILE_B)
#define NSTAGE 3
#define GEMM_SMEM_TOTAL (NSTAGE * STAGE_B)  // 92160 -> 2 CTAs/SM

__global__ __launch_bounds__(256, 2) void gemm2t(
    const __half* __restrict__ A,
    const __half* __restrict__ Bh, const __half* __restrict__ Bl,
    int M, int N, int K,
    long sA, long sB, long sC,
    float alpha, int mode, int nprod,
    void* __restrict__ C0)
{
    extern __shared__ char smem[];
    const uint32_t smem_base = smem_to_u32(smem);
    const int tid  = threadIdx.x;
    const int wid  = tid >> 5;
    const int lane = tid & 31;
    const int wm = wid & 1;        // 2 warps along M (64 rows each)
    const int wn = wid >> 1;       // 4 warps along N (32 cols each)
    const int z = blockIdx.z;

    A  += (long)z * sA;
    Bh += (long)z * sB;
    if (nprod == 2) Bl += (long)z * sB;

    const int m0 = blockIdx.y * 128;
    const int n0 = blockIdx.x * 128;

    float acc[4][4][4];
    #pragma unroll
    for (int i = 0; i < 4; i++)
        #pragma unroll
        for (int j = 0; j < 4; j++)
            #pragma unroll
            for (int c = 0; c < 4; c++) acc[i][j][c] = 0.0f;

    const int nslab = K / BKH;
    const int lrow = tid >> 2;        // 0..63
    const int lch  = tid & 3;

    // -------- async slab loader --------
    auto load_slab = [&](int s) {
        const long koff = (long)s * BKH + lch * 8;
        const uint32_t st = smem_base + (uint32_t)(s % NSTAGE) * STAGE_B;
        const uint32_t so = (uint32_t)(lrow * ROWB + lch * 16);
        #pragma unroll
        for (int i = 0; i < 2; i++) {
            const int r = lrow + 64 * i;
            const long ga = (long)(m0 + r) * K + koff;
            const long gb = (long)(n0 + r) * K + koff;
            const uint32_t ro = so + (uint32_t)i * (64 * ROWB);
            CP_ASYNC16(st +          ro, A  + ga);
            CP_ASYNC16(st + OFF_BH + ro, Bh + gb);
            if (nprod == 2) CP_ASYNC16(st + OFF_BL + ro, Bl + gb);
        }
    };

    load_slab(0); CP_ASYNC_COMMIT();
    if (nslab > 1) load_slab(1);
    CP_ASYNC_COMMIT();

    const int am = lane & 15;
    const int ac = (lane >> 4) << 3;
    const int bn = ((lane >> 4) << 3) + (lane & 7);
    const int bc = ((lane >> 3) & 1) << 3;

    for (int s = 0; s < nslab; s++) {
        CP_ASYNC_WAIT1();          // slab s resident (only s+1 may be pending)
        __syncthreads();

        const uint32_t st = smem_base + (uint32_t)(s % NSTAGE) * STAGE_B;
        #pragma unroll
        for (int k16 = 0; k16 < 2; k16++) {
            // ---- A fragments: 4 ldsm.x4 ----
            uint32_t ra[4][4];
            #pragma unroll
            for (int mi = 0; mi < 4; mi++) {
                const uint32_t ao =
                    (uint32_t)((wm * 64 + mi * 16 + am) * ROWH + k16 * 16 + ac) * 2;
                ldsm_x4(ra[mi], st + ao);
            }
            // ---- B pair 0 prologue ----
            uint32_t th[2][4], tl[2][4];
            const uint32_t bbase =
                (uint32_t)((wn * 32 + bn) * ROWH + k16 * 16 + bc) * 2;
            ldsm_x4(th[0], st + OFF_BH + bbase);
            if (nprod == 2) ldsm_x4(tl[0], st + OFF_BL + bbase);

            // issue next-next slab's loads behind the prologue ldsm latency
            if (k16 == 0) {
                if (s + 2 < nslab) load_slab(s + 2);
                CP_ASYNC_COMMIT();
            }

            // ---- pair loop (2 pairs of 16 cols) with one-ahead B prefetch ----
            #pragma unroll
            for (int pair = 0; pair < 2; pair++) {
                const int cur = pair & 1;
                if (pair < 1) {
                    const uint32_t bo = bbase + (uint32_t)(16 * ROWH) * 2;
                    ldsm_x4(th[cur ^ 1], st + OFF_BH + bo);
                    if (nprod == 2) ldsm_x4(tl[cur ^ 1], st + OFF_BL + bo);
                }
                #pragma unroll
                for (int nj = 0; nj < 2; nj++) {
                    const uint32_t bh2[2] = { th[cur][nj * 2], th[cur][nj * 2 + 1] };
                    #pragma unroll
                    for (int mi = 0; mi < 4; mi++)
                        mma16816(acc[mi][pair * 2 + nj], ra[mi], bh2);
                }
                if (nprod == 2) {
                    #pragma unroll
                    for (int nj = 0; nj < 2; nj++) {
                        const uint32_t bl2[2] = { tl[cur][nj * 2], tl[cur][nj * 2 + 1] };
                        #pragma unroll
                        for (int mi = 0; mi < 4; mi++)
                            mma16816(acc[mi][pair * 2 + nj], ra[mi], bl2);
                    }
                }
            }
        }
    }

    // -------- epilogue (register accumulators -> global) --------
    const int rq = lane >> 2;             // 0..7
    const int cq = (lane & 3) * 2;
    #pragma unroll
    for (int mi = 0; mi < 4; mi++) {
        #pragma unroll
        for (int ni = 0; ni < 4; ni++) {
            const int mA = m0 + wm * 64 + mi * 16 + rq;
            const int mB = mA + 8;
            const int n  = n0 + wn * 32 + ni * 8 + cq;
            const float v0 = acc[mi][ni][0] * alpha;
            const float v1 = acc[mi][ni][1] * alpha;
            const float v2 = acc[mi][ni][2] * alpha;
            const float v3 = acc[mi][ni][3] * alpha;
            if (mode == 0) {
                float* Cf = (float*)C0 + (size_t)z * sC;
                *(float2*)(Cf + (size_t)mA * N + n) = make_float2(v0, v1);
                *(float2*)(Cf + (size_t)mB * N + n) = make_float2(v2, v3);
            } else if (mode == 4) {
                *(__half2*)((__half*)C0 + (size_t)mA * N + n) =
                    __halves2half2(__float2half_rn(v0), __float2half_rn(v1));
                *(__half2*)((__half*)C0 + (size_t)mB * N + n) =
                    __halves2half2(__float2half_rn(v2), __float2half_rn(v3));
            } else {
                // transposed store: C[b][e][n] with m -> (b, nn)
                const float vv[4] = { v0, v1, v2, v3 };
                #pragma unroll
                for (int e = 0; e < 4; e++) {
                    const int m = (e < 2) ? mA : mB;
                    const int nn2 = n + (e & 1);
                    const int bi = m >> 11;
                    const int mm = m & (N_ - 1);
                    const size_t idx = ((size_t)bi * E_ + nn2) * N_ + mm;
                    ((__half*)C0)[idx] = __float2half_rn(vv[e]);
                }
            }
        }
    }
}

// ---------------------------------------------------------------------------
// elementwise conversions
// ---------------------------------------------------------------------------
__device__ __forceinline__ void split_store4(__half* h, __half* l, size_t idx, float4 v) {
    const __half h0 = __float2half_rn(v.x);
    const __half h1 = __float2half_rn(v.y);
    const __half h2 = __float2half_rn(v.z);
    const __half h3 = __float2half_rn(v.w);
    const __half l0 = __float2half_rn(v.x - __half2float(h0));
    const __half l1 = __float2half_rn(v.y - __half2float(h1));
    const __half l2 = __float2half_rn(v.z - __half2float(h2));
    const __half l3 = __float2half_rn(v.w - __half2float(h3));
    __half2* hp = (__half2*)(h + idx);
    __half2* lp = (__half2*)(l + idx);
    hp[0] = __halves2half2(h0, h1);  hp[1] = __halves2half2(h2, h3);
    lp[0] = __halves2half2(l0, l1);  lp[1] = __halves2half2(l2, l3);
}

// q, k, v -> plain fp16 (z = 0/1/2)
__global__ __launch_bounds__(256) void conv_in(
    const float* __restrict__ q, const float* __restrict__ k, const float* __restrict__ v,
    __half* __restrict__ q16, __half* __restrict__ k16, __half* __restrict__ v16, long n4)
{
    const int zz = blockIdx.z;
    const float* x = (zz == 0) ? q : (zz == 1) ? k : v;
    __half* h = (zz == 0) ? q16 : (zz == 1) ? k16 : v16;
    for (long i = blockIdx.x * 256 + threadIdx.x; i < n4; i += (long)gridDim.x * 256) {
        float4 vv = ((const float4*)x)[i];
        __half2* hp = (__half2*)(h + i * 4);
        hp[0] = __halves2half2(__float2half_rn(vv.x), __float2half_rn(vv.y));
        hp[1] = __halves2half2(__float2half_rn(vv.z), __float2half_rn(vv.w));
    }
}

// weights -> fp16 hi/lo (z = 0/1/2)
__global__ __launch_bounds__(256) void split_w(
    const float* __restrict__ Wq, const float* __restrict__ Wk, const float* __restrict__ Wv,
    __half* __restrict__ qh, __half* __restrict__ ql,
    __half* __restrict__ kh, __half* __restrict__ kl,
    __half* __restrict__ vh, __half* __restrict__ vl, long n4)
{
    const int zz = blockIdx.z;
    const float* x = (zz == 0) ? Wq : (zz == 1) ? Wk : Wv;
    __half* h = (zz == 0) ? qh : (zz == 1) ? kh : vh;
    __half* l = (zz == 0) ? ql : (zz == 1) ? kl : vl;
    for (long i = blockIdx.x * 256 + threadIdx.x; i < n4; i += (long)gridDim.x * 256) {
        float4 vv = ((const float4*)x)[i];
        split_store4(h, l, (size_t)i * 4, vv);
    }
}

// ---------------------------------------------------------------------------
// fused softmax (in place, fp32) + fp16 hi emission. One block per row.
// ---------------------------------------------------------------------------
__global__ __launch_bounds__(256) void softmax_fused(
    float* __restrict__ attn, __half* __restrict__ ah)
{
    const size_t row = blockIdx.x;
    float* p = attn + row * N_;
    const int t = threadIdx.x;
    __shared__ float red[8];

    float4 va = ((const float4*)p)[t];
    float4 vb = ((const float4*)p)[t + 256];

    float vmax = fmaxf(fmaxf(fmaxf(va.x, va.y), fmaxf(va.z, va.w)),
                       fmaxf(fmaxf(vb.x, vb.y), fmaxf(vb.z, vb.w)));
    #pragma unroll
    for (int o = 16; o > 0; o >>= 1) vmax = fmaxf(vmax, __shfl_xor_sync(0xFFFFFFFF, vmax, o));
    if ((t & 31) == 0) red[t >> 5] = vmax;
    __syncthreads();
    float m = fmaxf(fmaxf(fmaxf(red[0], red[1]), fmaxf(red[2], red[3])),
                    fmaxf(fmaxf(red[4], red[5]), fmaxf(red[6], red[7])));
    __syncthreads();

    va.x = __expf(va.x - m); va.y = __expf(va.y - m); va.z = __expf(va.z - m); va.w = __expf(va.w - m);
    vb.x = __expf(vb.x - m); vb.y = __expf(vb.y - m); vb.z = __expf(vb.z - m); vb.w = __expf(vb.w - m);

    float sum = va.x + va.y + va.z + va.w + vb.x + vb.y + vb.z + vb.w;
    #pragma unroll
    for (int o = 16; o > 0; o >>= 1) sum += __shfl_xor_sync(0xFFFFFFFF, sum, o);
    if ((t & 31) == 0) red[t >> 5] = sum;
    __syncthreads();
    const float inv = 1.0f / (red[0] + red[1] + red[2] + red[3] + red[4] + red[5] + red[6] + red[7]);

    va.x *= inv; va.y *= inv; va.z *= inv; va.w *= inv;
    vb.x *= inv; vb.y *= inv; vb.z *= inv; vb.w *= inv;

    ((float4*)p)[t]       = va;
    ((float4*)p)[t + 256] = vb;

    __half2* hp = (__half2*)(ah + row * N_ + (size_t)t * 4);
    hp[0] = __halves2half2(__float2half_rn(va.x), __float2half_rn(va.y));
    hp[1] = __halves2half2(__float2half_rn(va.z), __float2half_rn(va.w));
    __half2* hp2 = (__half2*)(ah + row * N_ + 1024 + (size_t)t * 4);
    hp2[0] = __halves2half2(__float2half_rn(vb.x), __float2half_rn(vb.y));
    hp2[1] = __halves2half2(__float2half_rn(vb.z), __float2half_rn(vb.w));
}

// ---------------------------------------------------------------------------
extern "C" void kernel_launch(void* const* d_in, const int* in_sizes, int n_in,
                              void* d_out, int out_size)
{
    const float* q  = (const float*)d_in[0];
    const float* k  = (const float*)d_in[1];
    const float* v  = (const float*)d_in[2];
    const float* Wq = (const float*)d_in[3];
    const float* Wk = (const float*)d_in[4];
    const float* Wv = (const float*)d_in[5];

    float* out  = (float*)d_out;                 // [B, N, E]
    float* attn = out + (long)B_ * N_ * E_;      // [B, N, N]

    cudaFuncSetAttribute(gemm2t, cudaFuncAttributeMaxDynamicSharedMemorySize, GEMM_SMEM_TOTAL);

    __half *q16, *k16, *v16;
    __half *Wqh, *Wql, *Wkh, *Wkl, *Wvh, *Wvl;
    __half *qph, *kph, *vpth, *ah;
    cudaGetSymbolAddress((void**)&q16, g_q16);
    cudaGetSymbolAddress((void**)&k16, g_k16);
    cudaGetSymbolAddress((void**)&v16, g_v16);
    cudaGetSymbolAddress((void**)&Wqh, g_Wqh); cudaGetSymbolAddress((void**)&Wql, g_Wql);
    cudaGetSymbolAddress((void**)&Wkh, g_Wkh); cudaGetSymbolAddress((void**)&Wkl, g_Wkl);
    cudaGetSymbolAddress((void**)&Wvh, g_Wvh); cudaGetSymbolAddress((void**)&Wvl, g_Wvl);
    cudaGetSymbolAddress((void**)&qph, g_qph);
    cudaGetSymbolAddress((void**)&kph, g_kph);
    cudaGetSymbolAddress((void**)&vpth, g_vpth);
    cudaGetSymbolAddress((void**)&ah, g_ah);

    const float c_eq  = rsqrtf((float)D_);
    const float scale = rsqrtf((float)E_);

    // 1-2) conversions (2 launches)
    {
        dim3 gi(2048, 1, 3);
        conv_in<<<gi, 256>>>(q, k, v, q16, k16, v16, QKV_ELEMS / 4);
        dim3 gw(256, 1, 3);
        split_w<<<gw, 256>>>(Wq, Wk, Wv, Wqh, Wql, Wkh, Wkl, Wvh, Wvl, W_ELEMS / 4);
    }

    // 3-5) projections: A = input fp16, B = W hi/lo (2-product), hi-only output
    {
        dim3 grid(E_ / 128, (B_ * N_) / 128, 1);
        gemm2t<<<grid, 256, GEMM_SMEM_TOTAL>>>(q16, Wqh, Wql, B_ * N_, E_, D_,
                                               0, 0, 0, c_eq, 4, 2, qph);
        gemm2t<<<grid, 256, GEMM_SMEM_TOTAL>>>(k16, Wkh, Wkl, B_ * N_, E_, D_,
                                               0, 0, 0, c_eq, 4, 2, kph);
        gemm2t<<<grid, 256, GEMM_SMEM_TOTAL>>>(v16, Wvh, Wvl, B_ * N_, E_, D_,
                                               0, 0, 0, c_eq, 2, 2, vpth);
    }

    // 6) dots = qp @ kp^T * scale -> attn region (fp32), single-product
    {
        dim3 grid(N_ / 128, N_ / 128, B_);
        gemm2t<<<grid, 256, GEMM_SMEM_TOTAL>>>(qph, kph, nullptr, N_, N_, E_,
                                               (long)N_ * E_, (long)N_ * E_, (long)N_ * N_,
                                               scale, 0, 1, attn);
    }

    // 7) softmax (in place) + fp16 hi emission
    softmax_fused<<<B_ * N_, 256>>>(attn, ah);

    // 8) out = attn @ vp (vp^T stored [b][e][n]), single-product
    {
        dim3 grid(E_ / 128, N_ / 128, B_);
        gemm2t<<<grid, 256, GEMM_SMEM_TOTAL>>>(ah, vpth, nullptr, N_, E_, N_,
                                               (long)N_ * N_, (long)E_ * N_, (long)N_ * E_,
                                               1.0f, 0, 1, out);
    }
}

// round 12
// speedup vs baseline: 4.3498x; 1.2934x over previous
#include <cuda_runtime.h>
#include <cuda_fp16.h>
#include <cstdint>
#include <math.h>

// Problem constants
#define B_ 8
#define N_ 2048
#define D_ 512
#define E_ 512

static constexpr long QKV_ELEMS  = (long)B_ * N_ * D_;   // 8,388,608
static constexpr long W_ELEMS    = (long)E_ * D_;        // 262,144
static constexpr long ATTN_ELEMS = (long)B_ * N_ * N_;   // 33,554,432

// ---------------- scratch (static device arrays; allocation-guard safe) ----
__device__ __half g_q16[QKV_ELEMS], g_k16[QKV_ELEMS], g_v16[QKV_ELEMS];
__device__ __half g_Wq16[W_ELEMS], g_Wk16[W_ELEMS], g_Wv16[W_ELEMS];
__device__ __half g_qph[QKV_ELEMS];                       // q-proj fp16
__device__ __half g_kph[QKV_ELEMS];                       // k-proj fp16
__device__ __half g_vpth[QKV_ELEMS];                      // v-proj fp16, [b][e][n]
__device__ __half g_ah[ATTN_ELEMS];                       // attn fp16

// ---------------- PTX helpers ----------------------------------------------
__device__ __forceinline__ uint32_t smem_to_u32(const void* p) {
    uint32_t a;
    asm("{ .reg .u64 t; cvta.to.shared.u64 t, %1; cvt.u32.u64 %0, t; }" : "=r"(a) : "l"(p));
    return a;
}

#define CP_ASYNC16(smem_u32, gptr) \
    asm volatile("cp.async.cg.shared.global [%0], [%1], 16;" :: "r"(smem_u32), "l"(gptr) : "memory")
#define CP_ASYNC_COMMIT() asm volatile("cp.async.commit_group;" ::: "memory")
#define CP_ASYNC_WAIT1()  asm volatile("cp.async.wait_group 1;" ::: "memory")

__device__ __forceinline__ void ldsm_x4(uint32_t* r, uint32_t addr) {
    asm volatile("ldmatrix.sync.aligned.m8n8.x4.shared.b16 {%0,%1,%2,%3}, [%4];"
        : "=r"(r[0]), "=r"(r[1]), "=r"(r[2]), "=r"(r[3]) : "r"(addr));
}

__device__ __forceinline__ void mma16816(float* c, const uint32_t* a, const uint32_t* b) {
    asm volatile(
        "mma.sync.aligned.m16n8k16.row.col.f32.f16.f16.f32 "
        "{%0,%1,%2,%3}, {%4,%5,%6,%7}, {%8,%9}, {%0,%1,%2,%3};"
        : "+f"(c[0]), "+f"(c[1]), "+f"(c[2]), "+f"(c[3])
        : "r"(a[0]), "r"(a[1]), "r"(a[2]), "r"(a[3]), "r"(b[0]), "r"(b[1]));
}

// ---------------------------------------------------------------------------
// single-product fp16 GEMM core:  C = alpha * A @ B^T
// A: [M,K] fp16 row-major K-contig; B: [N,K] fp16.
// mode 0: C0 fp32 [M,N] + z*sC;  mode 4: C0 fp16 [M,N];
// mode 2: C0 fp16 transposed [b][E_][N_].
// Block tile 128x128, BK=32, 8 warps (warp tile 64x32), 3-stage cp.async ring,
// 2 CTAs/SM (regs capped 126).
// ---------------------------------------------------------------------------
#define BKH 32                              // K halves per slab
#define ROWH 40                             // padded row length in halves
#define ROWB 80                             // row bytes
#define T_TILE_B (128 * ROWB)               // 10240
#define STAGE_B (2 * T_TILE_B)              // 20480: A, B
#define OFF_B (T_TILE_B)
#define NSTAGE 3
#define GEMM_SMEM_TOTAL (NSTAGE * STAGE_B)  // 61440 -> 2 CTAs/SM

__device__ __forceinline__ void gemm_core(
    const __half* __restrict__ A, const __half* __restrict__ B,
    int M, int N, int K, long sC, float alpha, int mode, int z,
    void* __restrict__ C0, uint32_t smem_base)
{
    const int tid  = threadIdx.x;
    const int wid  = tid >> 5;
    const int lane = tid & 31;
    const int wm = wid & 1;        // 2 warps along M (64 rows each)
    const int wn = wid >> 1;       // 4 warps along N (32 cols each)

    const int m0 = blockIdx.y * 128;
    const int n0 = blockIdx.x * 128;

    float acc[4][4][4];
    #pragma unroll
    for (int i = 0; i < 4; i++)
        #pragma unroll
        for (int j = 0; j < 4; j++)
            #pragma unroll
            for (int c = 0; c < 4; c++) acc[i][j][c] = 0.0f;

    const int nslab = K / BKH;
    const int lrow = tid >> 2;        // 0..63
    const int lch  = tid & 3;

    // -------- async slab loader: 4 cp.async per thread --------
    auto load_slab = [&](int s) {
        const long koff = (long)s * BKH + lch * 8;
        const uint32_t st = smem_base + (uint32_t)(s % NSTAGE) * STAGE_B;
        const uint32_t so = (uint32_t)(lrow * ROWB + lch * 16);
        #pragma unroll
        for (int i = 0; i < 2; i++) {
            const int r = lrow + 64 * i;
            const long ga = (long)(m0 + r) * K + koff;
            const long gb = (long)(n0 + r) * K + koff;
            const uint32_t ro = so + (uint32_t)i * (64 * ROWB);
            CP_ASYNC16(st +         ro, A + ga);
            CP_ASYNC16(st + OFF_B + ro, B + gb);
        }
    };

    load_slab(0); CP_ASYNC_COMMIT();
    if (nslab > 1) load_slab(1);
    CP_ASYNC_COMMIT();

    const int am = lane & 15;
    const int ac = (lane >> 4) << 3;
    const int bn = ((lane >> 4) << 3) + (lane & 7);
    const int bc = ((lane >> 3) & 1) << 3;

    for (int s = 0; s < nslab; s++) {
        CP_ASYNC_WAIT1();          // slab s resident (only s+1 may be pending)
        __syncthreads();

        const uint32_t st = smem_base + (uint32_t)(s % NSTAGE) * STAGE_B;
        #pragma unroll
        for (int k16 = 0; k16 < 2; k16++) {
            // ---- A fragments: 4 ldsm.x4 ----
            uint32_t ra[4][4];
            #pragma unroll
            for (int mi = 0; mi < 4; mi++) {
                const uint32_t ao =
                    (uint32_t)((wm * 64 + mi * 16 + am) * ROWH + k16 * 16 + ac) * 2;
                ldsm_x4(ra[mi], st + ao);
            }
            // ---- B pair 0 prologue ----
            uint32_t th[2][4];
            const uint32_t bbase =
                (uint32_t)((wn * 32 + bn) * ROWH + k16 * 16 + bc) * 2;
            ldsm_x4(th[0], st + OFF_B + bbase);

            // issue next-next slab's loads behind the prologue ldsm latency
            if (k16 == 0) {
                if (s + 2 < nslab) load_slab(s + 2);
                CP_ASYNC_COMMIT();
            }

            // ---- pair loop (2 pairs of 16 cols) with one-ahead B prefetch ----
            #pragma unroll
            for (int pair = 0; pair < 2; pair++) {
                const int cur = pair & 1;
                if (pair < 1) {
                    const uint32_t bo = bbase + (uint32_t)(16 * ROWH) * 2;
                    ldsm_x4(th[cur ^ 1], st + OFF_B + bo);
                }
                #pragma unroll
                for (int nj = 0; nj < 2; nj++) {
                    const uint32_t bh2[2] = { th[cur][nj * 2], th[cur][nj * 2 + 1] };
                    #pragma unroll
                    for (int mi = 0; mi < 4; mi++)
                        mma16816(acc[mi][pair * 2 + nj], ra[mi], bh2);
                }
            }
        }
    }

    // -------- epilogue --------
    const int rq = lane >> 2;             // 0..7
    const int cq = (lane & 3) * 2;
    #pragma unroll
    for (int mi = 0; mi < 4; mi++) {
        #pragma unroll
        for (int ni = 0; ni < 4; ni++) {
            const int mA = m0 + wm * 64 + mi * 16 + rq;
            const int mB = mA + 8;
            const int n  = n0 + wn * 32 + ni * 8 + cq;
            const float v0 = acc[mi][ni][0] * alpha;
            const float v1 = acc[mi][ni][1] * alpha;
            const float v2 = acc[mi][ni][2] * alpha;
            const float v3 = acc[mi][ni][3] * alpha;
            if (mode == 0) {
                float* Cf = (float*)C0 + (size_t)z * sC;
                *(float2*)(Cf + (size_t)mA * N + n) = make_float2(v0, v1);
                *(float2*)(Cf + (size_t)mB * N + n) = make_float2(v2, v3);
            } else if (mode == 4) {
                *(__half2*)((__half*)C0 + (size_t)mA * N + n) =
                    __halves2half2(__float2half_rn(v0), __float2half_rn(v1));
                *(__half2*)((__half*)C0 + (size_t)mB * N + n) =
                    __halves2half2(__float2half_rn(v2), __float2half_rn(v3));
            } else {
                // transposed store: C[b][e][n] with m -> (b, nn)
                const float vv[4] = { v0, v1, v2, v3 };
                #pragma unroll
                for (int e = 0; e < 4; e++) {
                    const int m = (e < 2) ? mA : mB;
                    const int nn2 = n + (e & 1);
                    const int bi = m >> 11;
                    const int mm = m & (N_ - 1);
                    const size_t idx = ((size_t)bi * E_ + nn2) * N_ + mm;
                    ((__half*)C0)[idx] = __float2half_rn(vv[e]);
                }
            }
        }
    }
}

// batched single-product GEMM (GEMM2 / GEMM3): z batches via strides
__global__ __launch_bounds__(256, 2) void gemm_b(
    const __half* __restrict__ A, const __half* __restrict__ B,
    int M, int N, int K, long sA, long sB, long sC,
    float alpha, void* __restrict__ C0)
{
    extern __shared__ char smem[];
    const int z = blockIdx.z;
    gemm_core(A + (long)z * sA, B + (long)z * sB, M, N, K, sC,
              alpha, 0, z, C0, smem_to_u32(smem));
}

// merged projections: z = 0 (q, mode4), 1 (k, mode4), 2 (v, mode2 transposed)
__global__ __launch_bounds__(256, 2) void gemm_proj(
    const __half* __restrict__ q16, const __half* __restrict__ k16,
    const __half* __restrict__ v16,
    const __half* __restrict__ Wq, const __half* __restrict__ Wk,
    const __half* __restrict__ Wv,
    __half* __restrict__ qph, __half* __restrict__ kph, __half* __restrict__ vpth,
    float alpha)
{
    extern __shared__ char smem[];
    const int z = blockIdx.z;
    const __half* A = (z == 0) ? q16 : (z == 1) ? k16 : v16;
    const __half* B = (z == 0) ? Wq  : (z == 1) ? Wk  : Wv;
    void* C = (z == 0) ? (void*)qph : (z == 1) ? (void*)kph : (void*)vpth;
    const int mode = (z == 2) ? 2 : 4;
    gemm_core(A, B, B_ * N_, E_, D_, 0, alpha, mode, 0, C, smem_to_u32(smem));
}

// ---------------------------------------------------------------------------
// elementwise conversions: fp32 -> fp16
// ---------------------------------------------------------------------------
__global__ __launch_bounds__(256) void conv3(
    const float* __restrict__ x0, const float* __restrict__ x1, const float* __restrict__ x2,
    __half* __restrict__ h0, __half* __restrict__ h1, __half* __restrict__ h2, long n4)
{
    const int zz = blockIdx.z;
    const float* x = (zz == 0) ? x0 : (zz == 1) ? x1 : x2;
    __half* h = (zz == 0) ? h0 : (zz == 1) ? h1 : h2;
    for (long i = blockIdx.x * 256 + threadIdx.x; i < n4; i += (long)gridDim.x * 256) {
        float4 vv = ((const float4*)x)[i];
        __half2* hp = (__half2*)(h + i * 4);
        hp[0] = __halves2half2(__float2half_rn(vv.x), __float2half_rn(vv.y));
        hp[1] = __halves2half2(__float2half_rn(vv.z), __float2half_rn(vv.w));
    }
}

// ---------------------------------------------------------------------------
// fused softmax (in place, fp32) + fp16 emission. One block per row.
// ---------------------------------------------------------------------------
__global__ __launch_bounds__(256) void softmax_fused(
    float* __restrict__ attn, __half* __restrict__ ah)
{
    const size_t row = blockIdx.x;
    float* p = attn + row * N_;
    const int t = threadIdx.x;
    __shared__ float red[8];

    float4 va = ((const float4*)p)[t];
    float4 vb = ((const float4*)p)[t + 256];

    float vmax = fmaxf(fmaxf(fmaxf(va.x, va.y), fmaxf(va.z, va.w)),
                       fmaxf(fmaxf(vb.x, vb.y), fmaxf(vb.z, vb.w)));
    #pragma unroll
    for (int o = 16; o > 0; o >>= 1) vmax = fmaxf(vmax, __shfl_xor_sync(0xFFFFFFFF, vmax, o));
    if ((t & 31) == 0) red[t >> 5] = vmax;
    __syncthreads();
    float m = fmaxf(fmaxf(fmaxf(red[0], red[1]), fmaxf(red[2], red[3])),
                    fmaxf(fmaxf(red[4], red[5]), fmaxf(red[6], red[7])));
    __syncthreads();

    va.x = __expf(va.x - m); va.y = __expf(va.y - m); va.z = __expf(va.z - m); va.w = __expf(va.w - m);
    vb.x = __expf(vb.x - m); vb.y = __expf(vb.y - m); vb.z = __expf(vb.z - m); vb.w = __expf(vb.w - m);

    float sum = va.x + va.y + va.z + va.w + vb.x + vb.y + vb.z + vb.w;
    #pragma unroll
    for (int o = 16; o > 0; o >>= 1) sum += __shfl_xor_sync(0xFFFFFFFF, sum, o);
    if ((t & 31) == 0) red[t >> 5] = sum;
    __syncthreads();
    const float inv = 1.0f / (red[0] + red[1] + red[2] + red[3] + red[4] + red[5] + red[6] + red[7]);

    va.x *= inv; va.y *= inv; va.z *= inv; va.w *= inv;
    vb.x *= inv; vb.y *= inv; vb.z *= inv; vb.w *= inv;

    ((float4*)p)[t]       = va;
    ((float4*)p)[t + 256] = vb;

    __half2* hp = (__half2*)(ah + row * N_ + (size_t)t * 4);
    hp[0] = __halves2half2(__float2half_rn(va.x), __float2half_rn(va.y));
    hp[1] = __halves2half2(__float2half_rn(va.z), __float2half_rn(va.w));
    __half2* hp2 = (__half2*)(ah + row * N_ + 1024 + (size_t)t * 4);
    hp2[0] = __halves2half2(__float2half_rn(vb.x), __float2half_rn(vb.y));
    hp2[1] = __halves2half2(__float2half_rn(vb.z), __float2half_rn(vb.w));
}

// ---------------------------------------------------------------------------
extern "C" void kernel_launch(void* const* d_in, const int* in_sizes, int n_in,
                              void* d_out, int out_size)
{
    const float* q  = (const float*)d_in[0];
    const float* k  = (const float*)d_in[1];
    const float* v  = (const float*)d_in[2];
    const float* Wq = (const float*)d_in[3];
    const float* Wk = (const float*)d_in[4];
    const float* Wv = (const float*)d_in[5];

    float* out  = (float*)d_out;                 // [B, N, E]
    float* attn = out + (long)B_ * N_ * E_;      // [B, N, N]

    cudaFuncSetAttribute(gemm_b, cudaFuncAttributeMaxDynamicSharedMemorySize, GEMM_SMEM_TOTAL);
    cudaFuncSetAttribute(gemm_proj, cudaFuncAttributeMaxDynamicSharedMemorySize, GEMM_SMEM_TOTAL);

    __half *q16, *k16, *v16, *Wq16, *Wk16, *Wv16;
    __half *qph, *kph, *vpth, *ah;
    cudaGetSymbolAddress((void**)&q16, g_q16);
    cudaGetSymbolAddress((void**)&k16, g_k16);
    cudaGetSymbolAddress((void**)&v16, g_v16);
    cudaGetSymbolAddress((void**)&Wq16, g_Wq16);
    cudaGetSymbolAddress((void**)&Wk16, g_Wk16);
    cudaGetSymbolAddress((void**)&Wv16, g_Wv16);
    cudaGetSymbolAddress((void**)&qph, g_qph);
    cudaGetSymbolAddress((void**)&kph, g_kph);
    cudaGetSymbolAddress((void**)&vpth, g_vpth);
    cudaGetSymbolAddress((void**)&ah, g_ah);

    const float c_eq  = rsqrtf((float)D_);
    const float scale = rsqrtf((float)E_);

    // 1-2) conversions (2 launches)
    {
        dim3 gi(2048, 1, 3);
        conv3<<<gi, 256>>>(q, k, v, q16, k16, v16, QKV_ELEMS / 4);
        dim3 gw(256, 1, 3);
        conv3<<<gw, 256>>>(Wq, Wk, Wv, Wq16, Wk16, Wv16, W_ELEMS / 4);
    }

    // 3) merged projections (one launch, 1536 CTAs)
    {
        dim3 grid(E_ / 128, (B_ * N_) / 128, 3);
        gemm_proj<<<grid, 256, GEMM_SMEM_TOTAL>>>(q16, k16, v16, Wq16, Wk16, Wv16,
                                                  qph, kph, vpth, c_eq);
    }

    // 4) dots = qp @ kp^T * scale -> attn region (fp32), batched
    {
        dim3 grid(N_ / 128, N_ / 128, B_);
        gemm_b<<<grid, 256, GEMM_SMEM_TOTAL>>>(qph, kph, N_, N_, E_,
                                               (long)N_ * E_, (long)N_ * E_, (long)N_ * N_,
                                               scale, attn);
    }

    // 5) softmax (in place) + fp16 emission
    softmax_fused<<<B_ * N_, 256>>>(attn, ah);

    // 6) out = attn @ vp (vp^T stored [b][e][n])
    {
        dim3 grid(E_ / 128, N_ / 128, B_);
        gemm_b<<<grid, 256, GEMM_SMEM_TOTAL>>>(ah, vpth, N_, E_, N_,
                                               (long)N_ * N_, (long)E_ * N_, (long)N_ * E_,
                                               1.0f, out);
    }
}

// round 13
// speedup vs baseline: 4.4461x; 1.0221x over previous
#include <cuda_runtime.h>
#include <cuda_fp16.h>
#include <cstdint>
#include <math.h>

// Problem constants
#define B_ 8
#define N_ 2048
#define D_ 512
#define E_ 512

static constexpr long QKV_ELEMS  = (long)B_ * N_ * D_;   // 8,388,608
static constexpr long W_ELEMS    = (long)E_ * D_;        // 262,144
static constexpr long ATTN_ELEMS = (long)B_ * N_ * N_;   // 33,554,432

// ---------------- scratch (static device arrays; allocation-guard safe) ----
__device__ __half g_q16[QKV_ELEMS], g_k16[QKV_ELEMS], g_v16[QKV_ELEMS];
__device__ __half g_Wq16t[W_ELEMS];                       // Wq^T [d][e]
__device__ __half g_Wk16t[W_ELEMS];                       // Wk^T [d][e]
__device__ __half g_Wv16[W_ELEMS];                        // Wv   [e][d]
__device__ __half g_Gt[W_ELEMS];                          // Gt[d'][d] = (Wq^T Wk)_{d,d'} * c^2 s
__device__ __half g_tmp[QKV_ELEMS];                       // tmp = q @ G'
__device__ __half g_vpth[QKV_ELEMS];                      // v-proj fp16, [b][e][n]
__device__ __half g_ah[ATTN_ELEMS];                       // attn fp16

// ---------------- PTX helpers ----------------------------------------------
__device__ __forceinline__ uint32_t smem_to_u32(const void* p) {
    uint32_t a;
    asm("{ .reg .u64 t; cvta.to.shared.u64 t, %1; cvt.u32.u64 %0, t; }" : "=r"(a) : "l"(p));
    return a;
}

#define CP_ASYNC16(smem_u32, gptr) \
    asm volatile("cp.async.cg.shared.global [%0], [%1], 16;" :: "r"(smem_u32), "l"(gptr) : "memory")
#define CP_ASYNC_COMMIT() asm volatile("cp.async.commit_group;" ::: "memory")
#define CP_ASYNC_WAIT1()  asm volatile("cp.async.wait_group 1;" ::: "memory")

__device__ __forceinline__ void ldsm_x4(uint32_t* r, uint32_t addr) {
    asm volatile("ldmatrix.sync.aligned.m8n8.x4.shared.b16 {%0,%1,%2,%3}, [%4];"
        : "=r"(r[0]), "=r"(r[1]), "=r"(r[2]), "=r"(r[3]) : "r"(addr));
}

__device__ __forceinline__ void mma16816(float* c, const uint32_t* a, const uint32_t* b) {
    asm volatile(
        "mma.sync.aligned.m16n8k16.row.col.f32.f16.f16.f32 "
        "{%0,%1,%2,%3}, {%4,%5,%6,%7}, {%8,%9}, {%0,%1,%2,%3};"
        : "+f"(c[0]), "+f"(c[1]), "+f"(c[2]), "+f"(c[3])
        : "r"(a[0]), "r"(a[1]), "r"(a[2]), "r"(a[3]), "r"(b[0]), "r"(b[1]));
}

// ---------------------------------------------------------------------------
// single-product fp16 GEMM core:  C = alpha * A @ B^T
// A: [M,K] fp16 row-major K-contig; B: [N,K] fp16.
// mode 0: C0 fp32 [M,N] + z*sC;  mode 4: C0 fp16 [M,N];
// mode 2: C0 fp16 transposed [b][E_][N_].
// Block tile 128x128, BK=32, 8 warps (warp tile 64x32), 3-stage cp.async ring,
// 2 CTAs/SM (regs capped 126).
// ---------------------------------------------------------------------------
#define BKH 32                              // K halves per slab
#define ROWH 40                             // padded row length in halves
#define ROWB 80                             // row bytes
#define T_TILE_B (128 * ROWB)               // 10240
#define STAGE_B (2 * T_TILE_B)              // 20480: A, B
#define OFF_B (T_TILE_B)
#define NSTAGE 3
#define GEMM_SMEM_TOTAL (NSTAGE * STAGE_B)  // 61440 -> 2 CTAs/SM

__device__ __forceinline__ void gemm_core(
    const __half* __restrict__ A, const __half* __restrict__ B,
    int M, int N, int K, long sC, float alpha, int mode, int z,
    void* __restrict__ C0, uint32_t smem_base)
{
    const int tid  = threadIdx.x;
    const int wid  = tid >> 5;
    const int lane = tid & 31;
    const int wm = wid & 1;        // 2 warps along M (64 rows each)
    const int wn = wid >> 1;       // 4 warps along N (32 cols each)

    const int m0 = blockIdx.y * 128;
    const int n0 = blockIdx.x * 128;

    float acc[4][4][4];
    #pragma unroll
    for (int i = 0; i < 4; i++)
        #pragma unroll
        for (int j = 0; j < 4; j++)
            #pragma unroll
            for (int c = 0; c < 4; c++) acc[i][j][c] = 0.0f;

    const int nslab = K / BKH;
    const int lrow = tid >> 2;        // 0..63
    const int lch  = tid & 3;

    // -------- async slab loader: 4 cp.async per thread --------
    auto load_slab = [&](int s) {
        const long koff = (long)s * BKH + lch * 8;
        const uint32_t st = smem_base + (uint32_t)(s % NSTAGE) * STAGE_B;
        const uint32_t so = (uint32_t)(lrow * ROWB + lch * 16);
        #pragma unroll
        for (int i = 0; i < 2; i++) {
            const int r = lrow + 64 * i;
            const long ga = (long)(m0 + r) * K + koff;
            const long gb = (long)(n0 + r) * K + koff;
            const uint32_t ro = so + (uint32_t)i * (64 * ROWB);
            CP_ASYNC16(st +         ro, A + ga);
            CP_ASYNC16(st + OFF_B + ro, B + gb);
        }
    };

    load_slab(0); CP_ASYNC_COMMIT();
    if (nslab > 1) load_slab(1);
    CP_ASYNC_COMMIT();

    const int am = lane & 15;
    const int ac = (lane >> 4) << 3;
    const int bn = ((lane >> 4) << 3) + (lane & 7);
    const int bc = ((lane >> 3) & 1) << 3;

    for (int s = 0; s < nslab; s++) {
        CP_ASYNC_WAIT1();          // slab s resident (only s+1 may be pending)
        __syncthreads();

        const uint32_t st = smem_base + (uint32_t)(s % NSTAGE) * STAGE_B;
        #pragma unroll
        for (int k16 = 0; k16 < 2; k16++) {
            // ---- A fragments: 4 ldsm.x4 ----
            uint32_t ra[4][4];
            #pragma unroll
            for (int mi = 0; mi < 4; mi++) {
                const uint32_t ao =
                    (uint32_t)((wm * 64 + mi * 16 + am) * ROWH + k16 * 16 + ac) * 2;
                ldsm_x4(ra[mi], st + ao);
            }
            // ---- B pair 0 prologue ----
            uint32_t th[2][4];
            const uint32_t bbase =
                (uint32_t)((wn * 32 + bn) * ROWH + k16 * 16 + bc) * 2;
            ldsm_x4(th[0], st + OFF_B + bbase);

            // issue next-next slab's loads behind the prologue ldsm latency
            if (k16 == 0) {
                if (s + 2 < nslab) load_slab(s + 2);
                CP_ASYNC_COMMIT();
            }

            // ---- pair loop (2 pairs of 16 cols) with one-ahead B prefetch ----
            #pragma unroll
            for (int pair = 0; pair < 2; pair++) {
                const int cur = pair & 1;
                if (pair < 1) {
                    const uint32_t bo = bbase + (uint32_t)(16 * ROWH) * 2;
                    ldsm_x4(th[cur ^ 1], st + OFF_B + bo);
                }
                #pragma unroll
                for (int nj = 0; nj < 2; nj++) {
                    const uint32_t bh2[2] = { th[cur][nj * 2], th[cur][nj * 2 + 1] };
                    #pragma unroll
                    for (int mi = 0; mi < 4; mi++)
                        mma16816(acc[mi][pair * 2 + nj], ra[mi], bh2);
                }
            }
        }
    }

    // -------- epilogue --------
    const int rq = lane >> 2;             // 0..7
    const int cq = (lane & 3) * 2;
    #pragma unroll
    for (int mi = 0; mi < 4; mi++) {
        #pragma unroll
        for (int ni = 0; ni < 4; ni++) {
            const int mA = m0 + wm * 64 + mi * 16 + rq;
            const int mB = mA + 8;
            const int n  = n0 + wn * 32 + ni * 8 + cq;
            const float v0 = acc[mi][ni][0] * alpha;
            const float v1 = acc[mi][ni][1] * alpha;
            const float v2 = acc[mi][ni][2] * alpha;
            const float v3 = acc[mi][ni][3] * alpha;
            if (mode == 0) {
                float* Cf = (float*)C0 + (size_t)z * sC;
                *(float2*)(Cf + (size_t)mA * N + n) = make_float2(v0, v1);
                *(float2*)(Cf + (size_t)mB * N + n) = make_float2(v2, v3);
            } else if (mode == 4) {
                *(__half2*)((__half*)C0 + (size_t)mA * N + n) =
                    __halves2half2(__float2half_rn(v0), __float2half_rn(v1));
                *(__half2*)((__half*)C0 + (size_t)mB * N + n) =
                    __halves2half2(__float2half_rn(v2), __float2half_rn(v3));
            } else {
                // transposed store: C[b][e][n] with m -> (b, nn)
                const float vv[4] = { v0, v1, v2, v3 };
                #pragma unroll
                for (int e = 0; e < 4; e++) {
                    const int m = (e < 2) ? mA : mB;
                    const int nn2 = n + (e & 1);
                    const int bi = m >> 11;
                    const int mm = m & (N_ - 1);
                    const size_t idx = ((size_t)bi * E_ + nn2) * N_ + mm;
                    ((__half*)C0)[idx] = __float2half_rn(vv[e]);
                }
            }
        }
    }
}

// batched single-product GEMM (dots / out): z batches via strides
__global__ __launch_bounds__(256, 2) void gemm_b(
    const __half* __restrict__ A, const __half* __restrict__ B,
    int M, int N, int K, long sA, long sB, long sC,
    float alpha, void* __restrict__ C0)
{
    extern __shared__ char smem[];
    const int z = blockIdx.z;
    gemm_core(A + (long)z * sA, B + (long)z * sB, M, N, K, sC,
              alpha, 0, z, C0, smem_to_u32(smem));
}

// non-batched generic GEMM (G precompute)
__global__ __launch_bounds__(256, 2) void gemm_s(
    const __half* __restrict__ A, const __half* __restrict__ B,
    int M, int N, int K, float alpha, int mode, void* __restrict__ C0)
{
    extern __shared__ char smem[];
    gemm_core(A, B, M, N, K, 0, alpha, mode, 0, C0, smem_to_u32(smem));
}

// merged: z = 0 (tmp = q16 @ Gt^T, mode 4), z = 1 (v-proj, mode 2 transposed)
__global__ __launch_bounds__(256, 2) void gemm_proj(
    const __half* __restrict__ q16, const __half* __restrict__ v16,
    const __half* __restrict__ Gt, const __half* __restrict__ Wv,
    __half* __restrict__ tmp, __half* __restrict__ vpth, float c_eq)
{
    extern __shared__ char smem[];
    const int z = blockIdx.z;
    const __half* A = (z == 0) ? q16 : v16;
    const __half* B = (z == 0) ? Gt  : Wv;
    void* C = (z == 0) ? (void*)tmp : (void*)vpth;
    const int mode = (z == 0) ? 4 : 2;
    const float alpha = (z == 0) ? 1.0f : c_eq;
    gemm_core(A, B, B_ * N_, E_, D_, 0, alpha, mode, 0, C, smem_to_u32(smem));
}

// ---------------------------------------------------------------------------
// elementwise conversions: fp32 -> fp16 (q/k/v straight)
// ---------------------------------------------------------------------------
__global__ __launch_bounds__(256) void conv3(
    const float* __restrict__ x0, const float* __restrict__ x1, const float* __restrict__ x2,
    __half* __restrict__ h0, __half* __restrict__ h1, __half* __restrict__ h2, long n4)
{
    const int zz = blockIdx.z;
    const float* x = (zz == 0) ? x0 : (zz == 1) ? x1 : x2;
    __half* h = (zz == 0) ? h0 : (zz == 1) ? h1 : h2;
    for (long i = blockIdx.x * 256 + threadIdx.x; i < n4; i += (long)gridDim.x * 256) {
        float4 vv = ((const float4*)x)[i];
        __half2* hp = (__half2*)(h + i * 4);
        hp[0] = __halves2half2(__float2half_rn(vv.x), __float2half_rn(vv.y));
        hp[1] = __halves2half2(__float2half_rn(vv.z), __float2half_rn(vv.w));
    }
}

// weights: z=0 Wq -> Wq16t (transposed), z=1 Wk -> Wk16t (transposed),
//          z=2 Wv -> Wv16 (straight)
__global__ __launch_bounds__(256) void conv_wt(
    const float* __restrict__ Wq, const float* __restrict__ Wk, const float* __restrict__ Wv,
    __half* __restrict__ Wqt, __half* __restrict__ Wkt, __half* __restrict__ Wv16)
{
    const int zz = blockIdx.z;
    const float* x = (zz == 0) ? Wq : (zz == 1) ? Wk : Wv;
    __half* o = (zz == 0) ? Wqt : (zz == 1) ? Wkt : Wv16;
    for (long i = blockIdx.x * 256 + threadIdx.x; i < W_ELEMS; i += (long)gridDim.x * 256) {
        const int e = (int)(i >> 9);          // row (E index)
        const int d = (int)(i & 511);         // col (D index)
        const __half h = __float2half_rn(x[i]);
        if (zz < 2) o[(size_t)d * E_ + e] = h;     // transposed [d][e]
        else        o[i] = h;                      // straight [e][d]
    }
}

// ---------------------------------------------------------------------------
// fused softmax (in place, fp32) + fp16 emission. One block per row.
// ---------------------------------------------------------------------------
__global__ __launch_bounds__(256) void softmax_fused(
    float* __restrict__ attn, __half* __restrict__ ah)
{
    const size_t row = blockIdx.x;
    float* p = attn + row * N_;
    const int t = threadIdx.x;
    __shared__ float red[8];

    float4 va = ((const float4*)p)[t];
    float4 vb = ((const float4*)p)[t + 256];

    float vmax = fmaxf(fmaxf(fmaxf(va.x, va.y), fmaxf(va.z, va.w)),
                       fmaxf(fmaxf(vb.x, vb.y), fmaxf(vb.z, vb.w)));
    #pragma unroll
    for (int o = 16; o > 0; o >>= 1) vmax = fmaxf(vmax, __shfl_xor_sync(0xFFFFFFFF, vmax, o));
    if ((t & 31) == 0) red[t >> 5] = vmax;
    __syncthreads();
    float m = fmaxf(fmaxf(fmaxf(red[0], red[1]), fmaxf(red[2], red[3])),
                    fmaxf(fmaxf(red[4], red[5]), fmaxf(red[6], red[7])));
    __syncthreads();

    va.x = __expf(va.x - m); va.y = __expf(va.y - m); va.z = __expf(va.z - m); va.w = __expf(va.w - m);
    vb.x = __expf(vb.x - m); vb.y = __expf(vb.y - m); vb.z = __expf(vb.z - m); vb.w = __expf(vb.w - m);

    float sum = va.x + va.y + va.z + va.w + vb.x + vb.y + vb.z + vb.w;
    #pragma unroll
    for (int o = 16; o > 0; o >>= 1) sum += __shfl_xor_sync(0xFFFFFFFF, sum, o);
    if ((t & 31) == 0) red[t >> 5] = sum;
    __syncthreads();
    const float inv = 1.0f / (red[0] + red[1] + red[2] + red[3] + red[4] + red[5] + red[6] + red[7]);

    va.x *= inv; va.y *= inv; va.z *= inv; va.w *= inv;
    vb.x *= inv; vb.y *= inv; vb.z *= inv; vb.w *= inv;

    ((float4*)p)[t]       = va;
    ((float4*)p)[t + 256] = vb;

    __half2* hp = (__half2*)(ah + row * N_ + (size_t)t * 4);
    hp[0] = __halves2half2(__float2half_rn(va.x), __float2half_rn(va.y));
    hp[1] = __halves2half2(__float2half_rn(va.z), __float2half_rn(va.w));
    __half2* hp2 = (__half2*)(ah + row * N_ + 1024 + (size_t)t * 4);
    hp2[0] = __halves2half2(__float2half_rn(vb.x), __float2half_rn(vb.y));
    hp2[1] = __halves2half2(__float2half_rn(vb.z), __float2half_rn(vb.w));
}

// ---------------------------------------------------------------------------
extern "C" void kernel_launch(void* const* d_in, const int* in_sizes, int n_in,
                              void* d_out, int out_size)
{
    const float* q  = (const float*)d_in[0];
    const float* k  = (const float*)d_in[1];
    const float* v  = (const float*)d_in[2];
    const float* Wq = (const float*)d_in[3];
    const float* Wk = (const float*)d_in[4];
    const float* Wv = (const float*)d_in[5];

    float* out  = (float*)d_out;                 // [B, N, E]
    float* attn = out + (long)B_ * N_ * E_;      // [B, N, N]

    cudaFuncSetAttribute(gemm_b, cudaFuncAttributeMaxDynamicSharedMemorySize, GEMM_SMEM_TOTAL);
    cudaFuncSetAttribute(gemm_s, cudaFuncAttributeMaxDynamicSharedMemorySize, GEMM_SMEM_TOTAL);
    cudaFuncSetAttribute(gemm_proj, cudaFuncAttributeMaxDynamicSharedMemorySize, GEMM_SMEM_TOTAL);

    __half *q16, *k16, *v16, *Wq16t, *Wk16t, *Wv16, *Gt, *tmp, *vpth, *ah;
    cudaGetSymbolAddress((void**)&q16, g_q16);
    cudaGetSymbolAddress((void**)&k16, g_k16);
    cudaGetSymbolAddress((void**)&v16, g_v16);
    cudaGetSymbolAddress((void**)&Wq16t, g_Wq16t);
    cudaGetSymbolAddress((void**)&Wk16t, g_Wk16t);
    cudaGetSymbolAddress((void**)&Wv16, g_Wv16);
    cudaGetSymbolAddress((void**)&Gt, g_Gt);
    cudaGetSymbolAddress((void**)&tmp, g_tmp);
    cudaGetSymbolAddress((void**)&vpth, g_vpth);
    cudaGetSymbolAddress((void**)&ah, g_ah);

    const float c_eq    = rsqrtf((float)D_);
    const float scale   = rsqrtf((float)E_);
    const float alpha_G = c_eq * c_eq * scale;   // 512^-1.5

    // 1) input conversions
    {
        dim3 gi(2048, 1, 3);
        conv3<<<gi, 256>>>(q, k, v, q16, k16, v16, QKV_ELEMS / 4);
    }
    // 2) weight conversions (Wq/Wk transposed for the G GEMM)
    {
        dim3 gw(256, 1, 3);
        conv_wt<<<gw, 256>>>(Wq, Wk, Wv, Wq16t, Wk16t, Wv16);
    }
    // 3) Gt[d'][d] = sum_e Wk[e][d'] * Wq[e][d] * alpha_G  (A=Wk^T, B=Wq^T)
    {
        dim3 grid(E_ / 128, D_ / 128, 1);
        gemm_s<<<grid, 256, GEMM_SMEM_TOTAL>>>(Wk16t, Wq16t, D_, D_, E_,
                                               alpha_G, 4, Gt);
    }
    // 4) merged: tmp = q16 @ Gt^T (z=0), vpt = v16 @ Wv16^T (z=1, transposed out)
    {
        dim3 grid(E_ / 128, (B_ * N_) / 128, 2);
        gemm_proj<<<grid, 256, GEMM_SMEM_TOTAL>>>(q16, v16, Gt, Wv16, tmp, vpth, c_eq);
    }
    // 5) dots = tmp @ k16^T -> attn region (fp32 logits), batched
    {
        dim3 grid(N_ / 128, N_ / 128, B_);
        gemm_b<<<grid, 256, GEMM_SMEM_TOTAL>>>(tmp, k16, N_, N_, D_,
                                               (long)N_ * D_, (long)N_ * D_, (long)N_ * N_,
                                               1.0f, attn);
    }
    // 6) softmax (in place) + fp16 emission
    softmax_fused<<<B_ * N_, 256>>>(attn, ah);

    // 7) out = attn @ vp (vp^T stored [b][e][n])
    {
        dim3 grid(E_ / 128, N_ / 128, B_);
        gemm_b<<<grid, 256, GEMM_SMEM_TOTAL>>>(ah, vpth, N_, E_, N_,
                                               (long)N_ * N_, (long)E_ * N_, (long)N_ * E_,
                                               1.0f, out);
    }
}